// round 10
// baseline (speedup 1.0000x reference)
#include <cuda_runtime.h>
#include <cuda_bf16.h>
#include <cstdint>
#include <math.h>

// ---------------- problem dims ----------------
#define NB 64
#define NT 512
#define ND 128
#define NH 512
#define NDS 32
#define NG4 (4 * NH)   // 2048

// ---------------- LSTM config ----------------
#define G 128          // persistent CTAs, 1/SM
#define TPB 384        // 12 warps: 8 hi (m16 x n16) + 4 lo (m16 x n16)
#define JPC 4          // hidden units per CTA -> 16 true z-cols
// SMEM layout (bytes)
#define H_OFF 0                    // h' [128 rows][1024B] = 131072
#define ZB_OFF 131072              // W' staging 32KB, then zhi/zlo (13KB)
#define MB_OFF 163840              // 4 mbarriers
#define LSTM_SMEM 163904

__device__ __forceinline__ uint32_t smem_u32(const void* p) {
    uint32_t a;
    asm("{ .reg .u64 t; cvta.to.shared.u64 t, %1; cvt.u32.u64 %0, t; }" : "=r"(a) : "l"(p));
    return a;
}
__device__ __forceinline__ uint16_t bf16_bits(float f) {
    return __bfloat16_as_ushort(__float2bfloat16(f));
}
__device__ __forceinline__ float bf16_val(float f) {
    return __bfloat162float(__float2bfloat16(f));
}
__device__ __forceinline__ uint16_t bf16_lo(float f) {
    return bf16_bits(f - bf16_val(f));
}
__device__ __forceinline__ float sigmoidf_(float x) { return 1.f / (1.f + expf(-x)); }
// fast gate nonlinearities (MUFU-based, ~2ulp; safe at extremes)
__device__ __forceinline__ float fsig(float x) { return 1.f / (1.f + __expf(-x)); }
__device__ __forceinline__ float ftanh(float x) {
    float ax = fabsf(x);
    float e = __expf(-2.f * ax);
    float r = (1.f - e) / (1.f + e);
    return copysignf(r, x);
}

__device__ __forceinline__ uint4 pack_hi8(float4 a, float4 b) {
    uint4 r;
    r.x = (uint32_t)bf16_bits(a.x) | ((uint32_t)bf16_bits(a.y) << 16);
    r.y = (uint32_t)bf16_bits(a.z) | ((uint32_t)bf16_bits(a.w) << 16);
    r.z = (uint32_t)bf16_bits(b.x) | ((uint32_t)bf16_bits(b.y) << 16);
    r.w = (uint32_t)bf16_bits(b.z) | ((uint32_t)bf16_bits(b.w) << 16);
    return r;
}
__device__ __forceinline__ uint4 pack_lo8(float4 a, float4 b) {
    uint4 r;
    r.x = (uint32_t)bf16_lo(a.x) | ((uint32_t)bf16_lo(a.y) << 16);
    r.y = (uint32_t)bf16_lo(a.z) | ((uint32_t)bf16_lo(a.w) << 16);
    r.z = (uint32_t)bf16_lo(b.x) | ((uint32_t)bf16_lo(b.y) << 16);
    r.w = (uint32_t)bf16_lo(b.z) | ((uint32_t)bf16_lo(b.w) << 16);
    return r;
}

#define LDSM_X4(r0, r1, r2, r3, addr) \
    asm volatile("ldmatrix.sync.aligned.m8n8.x4.shared.b16 {%0,%1,%2,%3}, [%4];" \
        : "=r"(r0), "=r"(r1), "=r"(r2), "=r"(r3) : "r"(addr))

#define MMA_BF16(c, a0, a1, a2, a3, b0, b1) \
    asm volatile("mma.sync.aligned.m16n8k16.row.col.f32.bf16.bf16.f32 " \
        "{%0,%1,%2,%3}, {%4,%5,%6,%7}, {%8,%9}, {%0,%1,%2,%3};" \
        : "+f"((c)[0]), "+f"((c)[1]), "+f"((c)[2]), "+f"((c)[3]) \
        : "r"(a0), "r"(a1), "r"(a2), "r"(a3), "r"(b0), "r"(b1))

#define CP16(dst, src) \
    asm volatile("cp.async.cg.shared.global [%0], [%1], 16;" :: "r"(dst), "l"(src))
#define CP_COMMIT() asm volatile("cp.async.commit_group;" ::: "memory")
#define CP_WAIT(n)  asm volatile("cp.async.wait_group %0;" :: "n"(n) : "memory")
#define CP_MBAR_ARRIVE(mbar) \
    asm volatile("cp.async.mbarrier.arrive.noinc.shared.b64 [%0];" \
                 :: "r"((uint32_t)(mbar)) : "memory")
#define MBARRIER_INIT(mbar, cnt) \
    asm volatile("mbarrier.init.shared.b64 [%0], %1;" :: "r"((uint32_t)(mbar)), "r"((uint32_t)(cnt)) : "memory")
#define MBARRIER_WAIT_PARITY(mbar, par) do { \
    uint32_t _m = (uint32_t)(mbar); uint32_t _p = (uint32_t)(par); uint32_t _d; \
    asm volatile("{\n\t.reg .pred p;\n\t" \
        "mbarrier.try_wait.parity.acquire.cta.shared::cta.b64 p, [%1], %2;\n\t" \
        "selp.b32 %0, 1, 0, p;\n\t}" : "=r"(_d) : "r"(_m), "r"(_p) : "memory"); \
    if (!_d) { \
        asm volatile("{\n\t.reg .pred P1;\n\t" \
            "WL_%=:\n\t" \
            "mbarrier.try_wait.parity.acquire.cta.shared::cta.b64 P1, [%0], %1, 0x989680;\n\t" \
            "@P1 bra.uni WD_%=;\n\t" \
            "bra.uni WL_%=;\n\t" \
            "WD_%=:\n\t}" :: "r"(_m), "r"(_p) : "memory"); \
    } } while (0)

// ---------------- global scratch ----------------
__device__ __nv_bfloat16 g_hh[2][NB][NH];       // h hi, double-buffered
__device__ __nv_bfloat16 g_hl[2][NB][NH];       // h lo, double-buffered
__device__ __nv_bfloat16 g_wt[2 * NG4][ND];     // wk transposed hi/lo
__device__ float g_xw[NT][NG4][NB];             // x@Wk + bias
__device__ float g_hs[NT][NH][NB];              // hidden states for dense
__device__ unsigned int g_cbar[4 * 32];         // per-chunk monotonic counters

__global__ void init_kernel() {
    int idx = blockIdx.x * blockDim.x + threadIdx.x;
    if (idx < 4 * 32) g_cbar[idx] = 0u;
    uint32_t* ph = reinterpret_cast<uint32_t*>(&g_hh[0][0][0]);
    uint32_t* pl = reinterpret_cast<uint32_t*>(&g_hl[0][0][0]);
    for (int i = idx; i < 2 * NB * NH / 2; i += gridDim.x * blockDim.x) {
        ph[i] = 0u; pl[i] = 0u;
    }
}

// ---- one-time: transpose + bf16 hi/lo split of wk ----
__global__ void wbf_kernel(const float* __restrict__ wk) {
    int n = blockIdx.x;
    int k = threadIdx.x;
    float w = wk[(size_t)k * NG4 + (n & (NG4 - 1))];
    g_wt[n][k] = (n < NG4) ? __ushort_as_bfloat16(bf16_bits(w))
                           : __ushort_as_bfloat16(bf16_lo(w));
}

// =====================================================================
// XW kernel (proven): g_xw[t][col][b] = x@wk + bias
// =====================================================================
#define XA_OFF 0
#define XB_OFF 32768
#define XZ_OFF 65536
#define XW_SMEM 132096

__global__ void __launch_bounds__(256, 1) xw_kernel(
    const float* __restrict__ x, const float* __restrict__ bias)
{
    extern __shared__ char smem[];
    const uint32_t sbu = smem_u32(smem);
    float* zb = reinterpret_cast<float*>(smem + XZ_OFF);
    const int tid = threadIdx.x, wid = tid >> 5, lane = tid & 31;
    const int t = blockIdx.x;
    const int s7 = lane & 7;

    for (int i = tid; i < 64 * 16; i += 256) {
        int b = i >> 4, cs = i & 15;
        const float4* xp = reinterpret_cast<const float4*>(
            x + ((size_t)b * NT + t) * ND + cs * 8);
        float4 x0 = xp[0], x1 = xp[1];
        *reinterpret_cast<uint4*>(smem + XA_OFF + b * 256 + ((cs ^ (b & 7)) << 4))
            = pack_hi8(x0, x1);
        int rl = b + 64;
        *reinterpret_cast<uint4*>(smem + XA_OFF + rl * 256 + ((cs ^ (rl & 7)) << 4))
            = pack_lo8(x0, x1);
    }
    __syncthreads();

    const int mslice = wid & 3, whalf = wid >> 2;
    uint32_t ar[8][2][4];
    {
        int row8 = ((lane >> 3) & 1) * 8 + s7;
        int acb = lane >> 4;
        #pragma unroll
        for (int ks = 0; ks < 8; ks++)
            #pragma unroll
            for (int mf = 0; mf < 2; mf++) {
                int row = mslice * 32 + mf * 16 + row8;
                uint32_t addr = sbu + XA_OFF + row * 256 +
                    (((ks * 2 + acb) ^ (row & 7)) << 4);
                LDSM_X4(ar[ks][mf][0], ar[ks][mf][1], ar[ks][mf][2], ar[ks][mf][3], addr);
            }
    }

    const int browl = ((lane >> 4) << 3) + s7;
    const int bcb = (lane >> 3) & 1;

    for (int cb = 0; cb < 32; cb++) {
        #pragma unroll
        for (int it = 0; it < 8; it++) {
            int i = it * 256 + tid;
            int row = i >> 4, cpi = i & 15;
            const __nv_bfloat16* src = (row < 64)
                ? &g_wt[cb * 64 + row][cpi * 8]
                : &g_wt[NG4 + cb * 64 + (row - 64)][cpi * 8];
            uint32_t dst = sbu + XB_OFF + row * 256 + ((cpi ^ (row & 7)) << 4);
            CP16(dst, src);
        }
        CP_COMMIT();
        CP_WAIT(0);
        __syncthreads();

        float acc[2][8][4];
        #pragma unroll
        for (int mf = 0; mf < 2; mf++)
            #pragma unroll
            for (int nf = 0; nf < 8; nf++)
                #pragma unroll
                for (int q = 0; q < 4; q++) acc[mf][nf][q] = 0.f;

        #pragma unroll
        for (int ks = 0; ks < 8; ks++) {
            #pragma unroll
            for (int q = 0; q < 4; q++) {
                int rowb = whalf * 64 + q * 16 + browl;
                uint32_t baddr = sbu + XB_OFF + rowb * 256 +
                    (((ks * 2 + bcb) ^ s7) << 4);
                uint32_t b0, b1, b2, b3;
                LDSM_X4(b0, b1, b2, b3, baddr);
                #pragma unroll
                for (int mf = 0; mf < 2; mf++) {
                    MMA_BF16(acc[mf][2 * q],     ar[ks][mf][0], ar[ks][mf][1],
                             ar[ks][mf][2], ar[ks][mf][3], b0, b1);
                    MMA_BF16(acc[mf][2 * q + 1], ar[ks][mf][0], ar[ks][mf][1],
                             ar[ks][mf][2], ar[ks][mf][3], b2, b3);
                }
            }
        }

        #pragma unroll
        for (int mf = 0; mf < 2; mf++)
            #pragma unroll
            for (int nf = 0; nf < 8; nf++) {
                int m = mslice * 32 + mf * 16 + (lane >> 2);
                int c = nf * 8 + 2 * (lane & 3);
                float* zp = zb + (size_t)(whalf * 128 + m) * 65 + c;
                zp[0] = acc[mf][nf][0];
                zp[1] = acc[mf][nf][1];
                zp[8 * 65] = acc[mf][nf][2];
                zp[8 * 65 + 1] = acc[mf][nf][3];
            }
        __syncthreads();

        for (int i = tid; i < 64 * 64; i += 256) {
            int b = i & 63, c = i >> 6;
            float z = zb[(size_t)b * 65 + c] + zb[(size_t)(128 + b) * 65 + c]
                    + zb[(size_t)(b + 64) * 65 + c] + zb[(size_t)(128 + b + 64) * 65 + c]
                    + bias[cb * 64 + c];
            g_xw[t][cb * 64 + c][b] = z;
        }
        __syncthreads();
    }
}

// =====================================================================
// Persistent LSTM: 12 warps, each one independent (m16 x n16) tile.
//   warps 0-7:  Whi x h'[n16 slice of 128]
//   warps 8-11: Wlo x hhi[n16 slice of 64]
// 3 warps/SMSP for ldsm-latency hiding; chunk-ordered mbarrier pipeline.
// =====================================================================
__global__ void __launch_bounds__(TPB, 1) lstm_kernel(
    const float* __restrict__ wr,
    float* __restrict__ out_h, float* __restrict__ out_c)
{
    extern __shared__ char smem[];
    const uint32_t sbu = smem_u32(smem);
    float* zhi = reinterpret_cast<float*>(smem + ZB_OFF);   // [128][17]
    float* zlo = zhi + 128 * 17;                            // [64][17]

    const int tid = threadIdx.x;
    const int wid = tid >> 5, lane = tid & 31;
    const int j0 = blockIdx.x * JPC;
    const int s7 = lane & 7;
    const bool hiW = (wid < 8);
    const int mychunk = blockIdx.x >> 5;    // producer chunk id

    if (tid == 0) {
        #pragma unroll
        for (int c = 0; c < 4; c++) MBARRIER_INIT(sbu + MB_OFF + 8 * c, TPB);
    }

    // ---- W' staging at ZB_OFF: rows m 0-15 = Whi, 16-31 = Wlo ----
    for (int i = tid; i < 32 * NH; i += TPB) {
        int m = i & 31, k = i >> 5;
        int c = m & 15, gate = c >> 2, jj = c & 3;
        float w = wr[(size_t)k * NG4 + gate * NH + j0 + jj];
        uint16_t bv = (m < 16) ? bf16_bits(w) : bf16_lo(w);
        *reinterpret_cast<uint16_t*>(smem + ZB_OFF + m * 1024 +
            ((((k >> 3) ^ (m & 7)) << 4) | ((k & 7) << 1))) = bv;
    }
    __syncthreads();

    // ---- a-frags: full k=512, m16 (Whi for w0-7, Wlo for w8-11) ----
    uint32_t ar[32][4];
    {
        int row = (hiW ? 0 : 16) + ((lane >> 3) & 1) * 8 + s7;
        int acb = lane >> 4;
        uint32_t rbase = sbu + ZB_OFF + row * 1024;
        #pragma unroll
        for (int ks = 0; ks < 32; ks++) {
            int chunk = ks * 2 + acb;
            LDSM_X4(ar[ks][0], ar[ks][1], ar[ks][2], ar[ks][3],
                    rbase + ((chunk ^ (row & 7)) << 4));
        }
    }
    __syncthreads();   // staging free; zhi/zlo reuse

    const int gb = tid & 63;
    const int gj = (tid >> 6) & 3;
    float c_state = 0.f;

    const int browl = ((lane >> 4) << 3) + s7;
    const int bcb = (lane >> 3) & 1;
    const int nbase = hiW ? wid * 16 : (wid - 8) * 16;
    const uint32_t bbase = sbu + H_OFF + (nbase + browl) * 1024;

    for (int t = 0; t < NT; t++) {
        // prefetch xw (DRAM; consumed at gates)
        float xwv[4];
        if (tid < 256) {
            #pragma unroll
            for (int g = 0; g < 4; g++)
                xwv[g] = __ldcg(&g_xw[t][g * NH + j0 + gj][gb]);
        }

        const int buf = t & 1;
        // ---- per-chunk: lane0 polls producer counter, warp issues cp.asyncs ----
        #pragma unroll
        for (int ch = 0; ch < 4; ch++) {
            if (lane == 0) {
                const unsigned int tgt = 32u * (unsigned int)t;
                const unsigned int* cp = &g_cbar[ch * 32];
                unsigned int cur;
                do {
                    asm volatile("ld.global.acquire.gpu.u32 %0, [%1];"
                                 : "=r"(cur) : "l"(cp));
                } while (cur < tgt);
            }
            __syncwarp();
            for (int i = tid; i < 2048; i += TPB) {
                int row = i >> 4, q = i & 15;
                const __nv_bfloat16* src = (row < 64)
                    ? &g_hh[buf][row][ch * 128 + q * 8]
                    : &g_hl[buf][row - 64][ch * 128 + q * 8];
                int gch = ch * 16 + q;
                uint32_t dst = sbu + H_OFF + row * 1024 + ((gch ^ (row & 7)) << 4);
                CP16(dst, src);
            }
            CP_MBAR_ARRIVE(sbu + MB_OFF + 8 * ch);
        }

        float acc[2][4];
        #pragma unroll
        for (int nf = 0; nf < 2; nf++)
            #pragma unroll
            for (int q = 0; q < 4; q++) acc[nf][q] = 0.f;

        // ---- chunk-ordered MMA: one ldsm.x4 + 2 MMA per ks ----
        #pragma unroll
        for (int c = 0; c < 4; c++) {
            MBARRIER_WAIT_PARITY(sbu + MB_OFF + 8 * c, t & 1);
            #pragma unroll
            for (int kk = 0; kk < 8; kk++) {
                int ks = c * 8 + kk;
                uint32_t off = (((ks * 2 + bcb) ^ s7) << 4);
                uint32_t b0, b1, b2, b3;
                LDSM_X4(b0, b1, b2, b3, bbase + off);
                MMA_BF16(acc[0], ar[ks][0], ar[ks][1], ar[ks][2], ar[ks][3], b0, b1);
                MMA_BF16(acc[1], ar[ks][0], ar[ks][1], ar[ks][2], ar[ks][3], b2, b3);
            }
        }

        // ---- epilogue: warp's (m16 x n16) tile -> zhi/zlo ----
        {
            int m = lane >> 2;
            float* zp = hiW ? zhi : zlo;
            #pragma unroll
            for (int nf = 0; nf < 2; nf++) {
                int n = nbase + nf * 8 + 2 * (lane & 3);
                zp[(size_t)n * 17 + m]           = acc[nf][0];
                zp[(size_t)(n + 1) * 17 + m]     = acc[nf][1];
                zp[(size_t)n * 17 + m + 8]       = acc[nf][2];
                zp[(size_t)(n + 1) * 17 + m + 8] = acc[nf][3];
            }
        }
        __syncthreads();

        // ---- gates: z = xw + Whi·hhi + Whi·hlo + Wlo·hhi ----
        if (tid < 256) {
            float z[4];
            #pragma unroll
            for (int g = 0; g < 4; g++) {
                int c = g * 4 + gj;
                z[g] = xwv[g] + zhi[(size_t)gb * 17 + c]
                     + zhi[(size_t)(gb + 64) * 17 + c]
                     + zlo[(size_t)gb * 17 + c];
            }
            float ig = fsig(z[0]);
            float fg = fsig(z[1]);
            float gv = ftanh(z[2]);
            float og = fsig(z[3]);
            c_state = fg * c_state + ig * gv;
            float hv = og * ftanh(c_state);
            int row = j0 + gj;
            __nv_bfloat16 hh = __float2bfloat16(hv);
            g_hh[(t + 1) & 1][gb][row] = hh;
            g_hl[(t + 1) & 1][gb][row] = __float2bfloat16(hv - __bfloat162float(hh));
            g_hs[t][row][gb] = hv;
            if (t == NT - 1) {
                out_h[(size_t)gb * NH + row] = hv;
                out_c[(size_t)gb * NH + row] = c_state;
            }
        }
        __syncthreads();

        // ---- producer publish: tid0 cumulative fence + one atomic ----
        if (t < NT - 1 && tid == 0) {
            __threadfence();
            atomicAdd(&g_cbar[mychunk * 32], 1u);
        }
    }
}

// ---------------- Dense(32, tanh) over all timesteps ----------------
#define DTPB 256
__global__ void __launch_bounds__(DTPB, 1) dense_kernel(
    const float* __restrict__ dw, const float* __restrict__ db,
    float* __restrict__ out)
{
    extern __shared__ float smemf[];
    float* hsm = smemf;
    float* wsm = smemf + NH * NB;
    int t = blockIdx.x, tid = threadIdx.x;
    {
        const float4* src = reinterpret_cast<const float4*>(&g_hs[t][0][0]);
        float4* dst = reinterpret_cast<float4*>(hsm);
        for (int i = tid; i < NH * NB / 4; i += DTPB) dst[i] = src[i];
        const float4* ws = reinterpret_cast<const float4*>(dw);
        float4* wd = reinterpret_cast<float4*>(wsm);
        for (int i = tid; i < NH * NDS / 4; i += DTPB) wd[i] = ws[i];
    }
    __syncthreads();

    int bg = tid & 15, dg = tid >> 4;
    float acc[4][2];
    #pragma unroll
    for (int bi = 0; bi < 4; bi++) { acc[bi][0] = 0.f; acc[bi][1] = 0.f; }
    #pragma unroll 4
    for (int k = 0; k < NH; k++) {
        float4 hv = *reinterpret_cast<const float4*>(&hsm[k * NB + bg * 4]);
        float2 wv = *reinterpret_cast<const float2*>(&wsm[k * NDS + dg * 2]);
        float hvv[4] = {hv.x, hv.y, hv.z, hv.w};
        #pragma unroll
        for (int bi = 0; bi < 4; bi++) {
            acc[bi][0] += hvv[bi] * wv.x;
            acc[bi][1] += hvv[bi] * wv.y;
        }
    }
    float b0 = db[dg * 2], b1 = db[dg * 2 + 1];
    #pragma unroll
    for (int bi = 0; bi < 4; bi++) {
        int b = bg * 4 + bi;
        size_t base = (size_t)b * NT * NDS + (size_t)t * NDS + dg * 2;
        out[base]     = tanhf(acc[bi][0] + b0);
        out[base + 1] = tanhf(acc[bi][1] + b1);
    }
}

#define DENSE_SMEM ((NH * NB + NH * NDS) * 4)

extern "C" void kernel_launch(void* const* d_in, const int* in_sizes, int n_in,
                              void* d_out, int out_size) {
    const float* x    = (const float*)d_in[0];
    const float* wk   = (const float*)d_in[1];
    const float* wr   = (const float*)d_in[2];
    const float* bias = (const float*)d_in[3];
    const float* dw   = (const float*)d_in[4];
    const float* db   = (const float*)d_in[5];
    float* out   = (float*)d_out;
    float* out_h = out + (size_t)NB * NT * NDS;
    float* out_c = out_h + (size_t)NB * NH;

    cudaFuncSetAttribute(xw_kernel,
                         cudaFuncAttributeMaxDynamicSharedMemorySize, XW_SMEM);
    cudaFuncSetAttribute(lstm_kernel,
                         cudaFuncAttributeMaxDynamicSharedMemorySize, LSTM_SMEM);
    cudaFuncSetAttribute(dense_kernel,
                         cudaFuncAttributeMaxDynamicSharedMemorySize, DENSE_SMEM);

    init_kernel<<<64, 256>>>();                          // 0
    wbf_kernel<<<2 * NG4, ND>>>(wk);                     // 1
    xw_kernel<<<NT, 256, XW_SMEM>>>(x, bias);            // 2
    lstm_kernel<<<G, TPB, LSTM_SMEM>>>(wr, out_h, out_c);// 3  <- profiled slot
    dense_kernel<<<NT, DTPB, DENSE_SMEM>>>(dw, db, out); // 4
}

// round 11
// speedup vs baseline: 1.6992x; 1.6992x over previous
#include <cuda_runtime.h>
#include <cuda_bf16.h>
#include <cstdint>
#include <math.h>

// ---------------- problem dims ----------------
#define NB 64
#define NT 512
#define ND 128
#define NH 512
#define NDS 32
#define NG4 (4 * NH)   // 2048

// ---------------- LSTM config (R7 shape + bulk-copy h) ----------------
#define G 128          // persistent CTAs, 1/SM
#define TPB 256        // 8 warps
#define JPC 4          // hidden units per CTA -> 16 true z-cols
// SMEM layout (bytes)
#define H_OFF 0                    // h' [4 chunks][128 rows][256B] = 131072
#define ZB_OFF 131072              // W' staging 32KB, then zhi/zlo (13KB)
#define MB_OFF 163840              // 4 mbarriers
#define LSTM_SMEM 163904

__device__ __forceinline__ uint32_t smem_u32(const void* p) {
    uint32_t a;
    asm("{ .reg .u64 t; cvta.to.shared.u64 t, %1; cvt.u32.u64 %0, t; }" : "=r"(a) : "l"(p));
    return a;
}
__device__ __forceinline__ uint16_t bf16_bits(float f) {
    return __bfloat16_as_ushort(__float2bfloat16(f));
}
__device__ __forceinline__ float bf16_val(float f) {
    return __bfloat162float(__float2bfloat16(f));
}
__device__ __forceinline__ uint16_t bf16_lo(float f) {
    return bf16_bits(f - bf16_val(f));
}
// fast gate nonlinearities (MUFU-based)
__device__ __forceinline__ float fsig(float x) { return 1.f / (1.f + __expf(-x)); }
__device__ __forceinline__ float ftanh(float x) {
    float ax = fabsf(x);
    float e = __expf(-2.f * ax);
    float r = (1.f - e) / (1.f + e);
    return copysignf(r, x);
}

__device__ __forceinline__ uint4 pack_hi8(float4 a, float4 b) {
    uint4 r;
    r.x = (uint32_t)bf16_bits(a.x) | ((uint32_t)bf16_bits(a.y) << 16);
    r.y = (uint32_t)bf16_bits(a.z) | ((uint32_t)bf16_bits(a.w) << 16);
    r.z = (uint32_t)bf16_bits(b.x) | ((uint32_t)bf16_bits(b.y) << 16);
    r.w = (uint32_t)bf16_bits(b.z) | ((uint32_t)bf16_bits(b.w) << 16);
    return r;
}
__device__ __forceinline__ uint4 pack_lo8(float4 a, float4 b) {
    uint4 r;
    r.x = (uint32_t)bf16_lo(a.x) | ((uint32_t)bf16_lo(a.y) << 16);
    r.y = (uint32_t)bf16_lo(a.z) | ((uint32_t)bf16_lo(a.w) << 16);
    r.z = (uint32_t)bf16_lo(b.x) | ((uint32_t)bf16_lo(b.y) << 16);
    r.w = (uint32_t)bf16_lo(b.z) | ((uint32_t)bf16_lo(b.w) << 16);
    return r;
}

#define LDSM_X4(r0, r1, r2, r3, addr) \
    asm volatile("ldmatrix.sync.aligned.m8n8.x4.shared.b16 {%0,%1,%2,%3}, [%4];" \
        : "=r"(r0), "=r"(r1), "=r"(r2), "=r"(r3) : "r"(addr))

#define MMA_BF16(c, a0, a1, a2, a3, b0, b1) \
    asm volatile("mma.sync.aligned.m16n8k16.row.col.f32.bf16.bf16.f32 " \
        "{%0,%1,%2,%3}, {%4,%5,%6,%7}, {%8,%9}, {%0,%1,%2,%3};" \
        : "+f"((c)[0]), "+f"((c)[1]), "+f"((c)[2]), "+f"((c)[3]) \
        : "r"(a0), "r"(a1), "r"(a2), "r"(a3), "r"(b0), "r"(b1))

#define CP16(dst, src) \
    asm volatile("cp.async.cg.shared.global [%0], [%1], 16;" :: "r"(dst), "l"(src))
#define CP_COMMIT() asm volatile("cp.async.commit_group;" ::: "memory")
#define CP_WAIT(n)  asm volatile("cp.async.wait_group %0;" :: "n"(n) : "memory")
#define MBARRIER_INIT(mbar, cnt) \
    asm volatile("mbarrier.init.shared.b64 [%0], %1;" :: "r"((uint32_t)(mbar)), "r"((uint32_t)(cnt)) : "memory")
#define MBARRIER_EXPECT_TX(mbar, bytes) \
    asm volatile("mbarrier.arrive.expect_tx.shared.b64 _, [%0], %1;" \
                 :: "r"((uint32_t)(mbar)), "r"((uint32_t)(bytes)) : "memory")
#define BULK_G2S(dst, src, bytes, mbar) \
    asm volatile("cp.async.bulk.shared::cta.global.mbarrier::complete_tx::bytes " \
                 "[%0], [%1], %2, [%3];" \
                 :: "r"((uint32_t)(dst)), "l"(src), "r"((uint32_t)(bytes)), \
                    "r"((uint32_t)(mbar)) : "memory")
#define MBARRIER_WAIT_PARITY(mbar, par) do { \
    uint32_t _m = (uint32_t)(mbar); uint32_t _p = (uint32_t)(par); uint32_t _d; \
    asm volatile("{\n\t.reg .pred p;\n\t" \
        "mbarrier.try_wait.parity.acquire.cta.shared::cta.b64 p, [%1], %2;\n\t" \
        "selp.b32 %0, 1, 0, p;\n\t}" : "=r"(_d) : "r"(_m), "r"(_p) : "memory"); \
    if (!_d) { \
        asm volatile("{\n\t.reg .pred P1;\n\t" \
            "WL_%=:\n\t" \
            "mbarrier.try_wait.parity.acquire.cta.shared::cta.b64 P1, [%0], %1, 0x989680;\n\t" \
            "@P1 bra.uni WD_%=;\n\t" \
            "bra.uni WL_%=;\n\t" \
            "WD_%=:\n\t}" :: "r"(_m), "r"(_p) : "memory"); \
    } } while (0)

// ---------------- global scratch ----------------
// h in the exact swizzled SMEM image: [buf][chunk][row][256B]
__device__ __align__(128) uint8_t g_hb[2][4][128][256];
__device__ __nv_bfloat16 g_wt[2 * NG4][ND];     // wk transposed hi/lo
__device__ float g_xw[NT][NG4][NB];             // x@Wk + bias
__device__ float g_hs[NT][NH][NB];              // hidden states for dense
__device__ unsigned int g_cbar[4 * 32];         // per-chunk monotonic counters

__global__ void init_kernel() {
    int idx = blockIdx.x * blockDim.x + threadIdx.x;
    if (idx < 4 * 32) g_cbar[idx] = 0u;
    uint32_t* p = reinterpret_cast<uint32_t*>(&g_hb[0][0][0][0]);
    for (int i = idx; i < (int)(sizeof(g_hb) / 4); i += gridDim.x * blockDim.x)
        p[i] = 0u;
}

// ---- one-time: transpose + bf16 hi/lo split of wk ----
__global__ void wbf_kernel(const float* __restrict__ wk) {
    int n = blockIdx.x;
    int k = threadIdx.x;
    float w = wk[(size_t)k * NG4 + (n & (NG4 - 1))];
    g_wt[n][k] = (n < NG4) ? __ushort_as_bfloat16(bf16_bits(w))
                           : __ushort_as_bfloat16(bf16_lo(w));
}

// =====================================================================
// XW kernel (proven): g_xw[t][col][b] = x@wk + bias
// =====================================================================
#define XA_OFF 0
#define XB_OFF 32768
#define XZ_OFF 65536
#define XW_SMEM 132096

__global__ void __launch_bounds__(256, 1) xw_kernel(
    const float* __restrict__ x, const float* __restrict__ bias)
{
    extern __shared__ char smem[];
    const uint32_t sbu = smem_u32(smem);
    float* zb = reinterpret_cast<float*>(smem + XZ_OFF);
    const int tid = threadIdx.x, wid = tid >> 5, lane = tid & 31;
    const int t = blockIdx.x;
    const int s7 = lane & 7;

    for (int i = tid; i < 64 * 16; i += 256) {
        int b = i >> 4, cs = i & 15;
        const float4* xp = reinterpret_cast<const float4*>(
            x + ((size_t)b * NT + t) * ND + cs * 8);
        float4 x0 = xp[0], x1 = xp[1];
        *reinterpret_cast<uint4*>(smem + XA_OFF + b * 256 + ((cs ^ (b & 7)) << 4))
            = pack_hi8(x0, x1);
        int rl = b + 64;
        *reinterpret_cast<uint4*>(smem + XA_OFF + rl * 256 + ((cs ^ (rl & 7)) << 4))
            = pack_lo8(x0, x1);
    }
    __syncthreads();

    const int mslice = wid & 3, whalf = wid >> 2;
    uint32_t ar[8][2][4];
    {
        int row8 = ((lane >> 3) & 1) * 8 + s7;
        int acb = lane >> 4;
        #pragma unroll
        for (int ks = 0; ks < 8; ks++)
            #pragma unroll
            for (int mf = 0; mf < 2; mf++) {
                int row = mslice * 32 + mf * 16 + row8;
                uint32_t addr = sbu + XA_OFF + row * 256 +
                    (((ks * 2 + acb) ^ (row & 7)) << 4);
                LDSM_X4(ar[ks][mf][0], ar[ks][mf][1], ar[ks][mf][2], ar[ks][mf][3], addr);
            }
    }

    const int browl = ((lane >> 4) << 3) + s7;
    const int bcb = (lane >> 3) & 1;

    for (int cb = 0; cb < 32; cb++) {
        #pragma unroll
        for (int it = 0; it < 8; it++) {
            int i = it * 256 + tid;
            int row = i >> 4, cpi = i & 15;
            const __nv_bfloat16* src = (row < 64)
                ? &g_wt[cb * 64 + row][cpi * 8]
                : &g_wt[NG4 + cb * 64 + (row - 64)][cpi * 8];
            uint32_t dst = sbu + XB_OFF + row * 256 + ((cpi ^ (row & 7)) << 4);
            CP16(dst, src);
        }
        CP_COMMIT();
        CP_WAIT(0);
        __syncthreads();

        float acc[2][8][4];
        #pragma unroll
        for (int mf = 0; mf < 2; mf++)
            #pragma unroll
            for (int nf = 0; nf < 8; nf++)
                #pragma unroll
                for (int q = 0; q < 4; q++) acc[mf][nf][q] = 0.f;

        #pragma unroll
        for (int ks = 0; ks < 8; ks++) {
            #pragma unroll
            for (int q = 0; q < 4; q++) {
                int rowb = whalf * 64 + q * 16 + browl;
                uint32_t baddr = sbu + XB_OFF + rowb * 256 +
                    (((ks * 2 + bcb) ^ s7) << 4);
                uint32_t b0, b1, b2, b3;
                LDSM_X4(b0, b1, b2, b3, baddr);
                #pragma unroll
                for (int mf = 0; mf < 2; mf++) {
                    MMA_BF16(acc[mf][2 * q],     ar[ks][mf][0], ar[ks][mf][1],
                             ar[ks][mf][2], ar[ks][mf][3], b0, b1);
                    MMA_BF16(acc[mf][2 * q + 1], ar[ks][mf][0], ar[ks][mf][1],
                             ar[ks][mf][2], ar[ks][mf][3], b2, b3);
                }
            }
        }

        #pragma unroll
        for (int mf = 0; mf < 2; mf++)
            #pragma unroll
            for (int nf = 0; nf < 8; nf++) {
                int m = mslice * 32 + mf * 16 + (lane >> 2);
                int c = nf * 8 + 2 * (lane & 3);
                float* zp = zb + (size_t)(whalf * 128 + m) * 65 + c;
                zp[0] = acc[mf][nf][0];
                zp[1] = acc[mf][nf][1];
                zp[8 * 65] = acc[mf][nf][2];
                zp[8 * 65 + 1] = acc[mf][nf][3];
            }
        __syncthreads();

        for (int i = tid; i < 64 * 64; i += 256) {
            int b = i & 63, c = i >> 6;
            float z = zb[(size_t)b * 65 + c] + zb[(size_t)(128 + b) * 65 + c]
                    + zb[(size_t)(b + 64) * 65 + c] + zb[(size_t)(128 + b + 64) * 65 + c]
                    + bias[cb * 64 + c];
            g_xw[t][cb * 64 + c][b] = z;
        }
        __syncthreads();
    }
}

// =====================================================================
// Persistent LSTM (R7 tiling). h broadcast = 4 x 32KB cp.async.bulk
// (one instruction each) instead of 2048 scalar cp.asyncs. Producers
// write h pre-swizzled into g_hb; fine-grained chunk counters.
// =====================================================================
__global__ void __launch_bounds__(TPB, 1) lstm_kernel(
    const float* __restrict__ wr,
    float* __restrict__ out_h, float* __restrict__ out_c)
{
    extern __shared__ char smem[];
    const uint32_t sbu = smem_u32(smem);
    float* zhi = reinterpret_cast<float*>(smem + ZB_OFF);   // [128][17]
    float* zlo = zhi + 128 * 17;                            // [64][17]

    const int tid = threadIdx.x;
    const int wid = tid >> 5, lane = tid & 31;
    const int j0 = blockIdx.x * JPC;
    const int s7 = lane & 7;
    const bool hiW = (wid < 4);
    const int mychunk = blockIdx.x >> 5;    // producer chunk id

    if (tid == 0) {
        #pragma unroll
        for (int c = 0; c < 4; c++) MBARRIER_INIT(sbu + MB_OFF + 8 * c, 1);
    }

    // ---- W' staging at ZB_OFF: rows m 0-15 = Whi, 16-31 = Wlo (1024B rows) ----
    for (int i = tid; i < 32 * NH; i += TPB) {
        int m = i & 31, k = i >> 5;
        int c = m & 15, gate = c >> 2, jj = c & 3;
        float w = wr[(size_t)k * NG4 + gate * NH + j0 + jj];
        uint16_t bv = (m < 16) ? bf16_bits(w) : bf16_lo(w);
        *reinterpret_cast<uint16_t*>(smem + ZB_OFF + m * 1024 +
            ((((k >> 3) ^ (m & 7)) << 4) | ((k & 7) << 1))) = bv;
    }
    __syncthreads();

    // ---- a-frags: full k=512, m16 (Whi for w0-3, Wlo for w4-7) ----
    uint32_t ar[32][4];
    {
        int row = (hiW ? 0 : 16) + ((lane >> 3) & 1) * 8 + s7;
        int acb = lane >> 4;
        uint32_t rbase = sbu + ZB_OFF + row * 1024;
        #pragma unroll
        for (int ks = 0; ks < 32; ks++) {
            int chunk = ks * 2 + acb;
            LDSM_X4(ar[ks][0], ar[ks][1], ar[ks][2], ar[ks][3],
                    rbase + ((chunk ^ (row & 7)) << 4));
        }
    }
    __syncthreads();   // staging free; zhi/zlo reuse

    const int gb = tid & 63;
    const int gj = (tid >> 6) & 3;
    float c_state = 0.f;

    const int browl = ((lane >> 4) << 3) + s7;
    const int bcb = (lane >> 3) & 1;
    const int rowsl = (hiW ? wid * 32 : (wid - 4) * 16) + browl;

    // producer h-write addresses (pre-swizzled image)
    const int jrow = j0 + gj;
    const int pchunk = jrow >> 7;
    const int pcs = (jrow >> 3) & 15;
    const int pwi = (jrow & 7) * 2;
    const size_t poff_hi = (size_t)pchunk * 32768 + (size_t)gb * 256 +
                           ((pcs ^ (gb & 7)) << 4) + pwi;
    const size_t poff_lo = poff_hi + 64 * 256;   // (gb+64)&7 == gb&7

    for (int t = 0; t < NT; t++) {
        // prefetch xw (DRAM; consumed at gates)
        float xwv[4];
        #pragma unroll
        for (int g = 0; g < 4; g++)
            xwv[g] = __ldcg(&g_xw[t][g * NH + j0 + gj][gb]);

        const int buf = t & 1;
        // ---- tid0: per chunk poll counter, then ONE 32KB bulk copy ----
        if (tid == 0) {
            const uint8_t* hsrc = &g_hb[buf][0][0][0];
            #pragma unroll
            for (int ch = 0; ch < 4; ch++) {
                const unsigned int tgt = 32u * (unsigned int)t;
                const unsigned int* cp = &g_cbar[ch * 32];
                unsigned int cur;
                do {
                    asm volatile("ld.global.acquire.gpu.u32 %0, [%1];"
                                 : "=r"(cur) : "l"(cp));
                } while (cur < tgt);
                MBARRIER_EXPECT_TX(sbu + MB_OFF + 8 * ch, 32768);
                BULK_G2S(sbu + H_OFF + ch * 32768, hsrc + (size_t)ch * 32768,
                         32768, sbu + MB_OFF + 8 * ch);
            }
        }

        float acc[4][4];
        #pragma unroll
        for (int nf = 0; nf < 4; nf++)
            #pragma unroll
            for (int q = 0; q < 4; q++) acc[nf][q] = 0.f;

        // ---- chunk-ordered MMA ----
        #pragma unroll
        for (int c = 0; c < 4; c++) {
            MBARRIER_WAIT_PARITY(sbu + MB_OFF + 8 * c, t & 1);
            uint32_t base0 = sbu + H_OFF + c * 32768 + rowsl * 256;
            if (hiW) {
                #pragma unroll
                for (int kk = 0; kk < 8; kk++) {
                    int ks = c * 8 + kk;
                    uint32_t off = (((kk * 2 + bcb) ^ s7) << 4);
                    uint32_t b00, b01, b10, b11, b20, b21, b30, b31;
                    LDSM_X4(b00, b01, b10, b11, base0 + off);
                    LDSM_X4(b20, b21, b30, b31, base0 + 16 * 256 + off);
                    MMA_BF16(acc[0], ar[ks][0], ar[ks][1], ar[ks][2], ar[ks][3], b00, b01);
                    MMA_BF16(acc[1], ar[ks][0], ar[ks][1], ar[ks][2], ar[ks][3], b10, b11);
                    MMA_BF16(acc[2], ar[ks][0], ar[ks][1], ar[ks][2], ar[ks][3], b20, b21);
                    MMA_BF16(acc[3], ar[ks][0], ar[ks][1], ar[ks][2], ar[ks][3], b30, b31);
                }
            } else {
                #pragma unroll
                for (int kk = 0; kk < 8; kk++) {
                    int ks = c * 8 + kk;
                    uint32_t off = (((kk * 2 + bcb) ^ s7) << 4);
                    uint32_t b00, b01, b10, b11;
                    LDSM_X4(b00, b01, b10, b11, base0 + off);
                    MMA_BF16(acc[0], ar[ks][0], ar[ks][1], ar[ks][2], ar[ks][3], b00, b01);
                    MMA_BF16(acc[1], ar[ks][0], ar[ks][1], ar[ks][2], ar[ks][3], b10, b11);
                }
            }
        }

        // ---- epilogue ----
        if (hiW) {
            #pragma unroll
            for (int nf = 0; nf < 4; nf++) {
                int m = lane >> 2;
                int n = wid * 32 + nf * 8 + 2 * (lane & 3);
                zhi[(size_t)n * 17 + m]            = acc[nf][0];
                zhi[(size_t)(n + 1) * 17 + m]      = acc[nf][1];
                zhi[(size_t)n * 17 + m + 8]        = acc[nf][2];
                zhi[(size_t)(n + 1) * 17 + m + 8]  = acc[nf][3];
            }
        } else {
            #pragma unroll
            for (int nf = 0; nf < 2; nf++) {
                int m = lane >> 2;
                int n = (wid - 4) * 16 + nf * 8 + 2 * (lane & 3);
                zlo[(size_t)n * 17 + m]            = acc[nf][0];
                zlo[(size_t)(n + 1) * 17 + m]      = acc[nf][1];
                zlo[(size_t)n * 17 + m + 8]        = acc[nf][2];
                zlo[(size_t)(n + 1) * 17 + m + 8]  = acc[nf][3];
            }
        }
        __syncthreads();

        // ---- gates: z = xw + Whi·hhi + Whi·hlo + Wlo·hhi ----
        {
            float z[4];
            #pragma unroll
            for (int g = 0; g < 4; g++) {
                int c = g * 4 + gj;
                z[g] = xwv[g] + zhi[(size_t)gb * 17 + c]
                     + zhi[(size_t)(gb + 64) * 17 + c]
                     + zlo[(size_t)gb * 17 + c];
            }
            float ig = fsig(z[0]);
            float fg = fsig(z[1]);
            float gv = ftanh(z[2]);
            float og = fsig(z[3]);
            c_state = fg * c_state + ig * gv;
            float hv = og * ftanh(c_state);
            __nv_bfloat16 hh = __float2bfloat16(hv);
            __nv_bfloat16 hl = __float2bfloat16(hv - __bfloat162float(hh));
            uint8_t* hdst = &g_hb[(t + 1) & 1][0][0][0];
            *reinterpret_cast<uint16_t*>(hdst + poff_hi) = __bfloat16_as_ushort(hh);
            *reinterpret_cast<uint16_t*>(hdst + poff_lo) = __bfloat16_as_ushort(hl);
            g_hs[t][jrow][gb] = hv;
            if (t == NT - 1) {
                out_h[(size_t)gb * NH + jrow] = hv;
                out_c[(size_t)gb * NH + jrow] = c_state;
            }
        }
        __syncthreads();

        // ---- producer publish: tid0 cumulative fence + one atomic ----
        if (t < NT - 1 && tid == 0) {
            __threadfence();
            atomicAdd(&g_cbar[mychunk * 32], 1u);
        }
    }
}

// ---------------- Dense(32, tanh) over all timesteps ----------------
#define DTPB 256
__global__ void __launch_bounds__(DTPB, 1) dense_kernel(
    const float* __restrict__ dw, const float* __restrict__ db,
    float* __restrict__ out)
{
    extern __shared__ float smemf[];
    float* hsm = smemf;
    float* wsm = smemf + NH * NB;
    int t = blockIdx.x, tid = threadIdx.x;
    {
        const float4* src = reinterpret_cast<const float4*>(&g_hs[t][0][0]);
        float4* dst = reinterpret_cast<float4*>(hsm);
        for (int i = tid; i < NH * NB / 4; i += DTPB) dst[i] = src[i];
        const float4* ws = reinterpret_cast<const float4*>(dw);
        float4* wd = reinterpret_cast<float4*>(wsm);
        for (int i = tid; i < NH * NDS / 4; i += DTPB) wd[i] = ws[i];
    }
    __syncthreads();

    int bg = tid & 15, dg = tid >> 4;
    float acc[4][2];
    #pragma unroll
    for (int bi = 0; bi < 4; bi++) { acc[bi][0] = 0.f; acc[bi][1] = 0.f; }
    #pragma unroll 4
    for (int k = 0; k < NH; k++) {
        float4 hv = *reinterpret_cast<const float4*>(&hsm[k * NB + bg * 4]);
        float2 wv = *reinterpret_cast<const float2*>(&wsm[k * NDS + dg * 2]);
        float hvv[4] = {hv.x, hv.y, hv.z, hv.w};
        #pragma unroll
        for (int bi = 0; bi < 4; bi++) {
            acc[bi][0] += hvv[bi] * wv.x;
            acc[bi][1] += hvv[bi] * wv.y;
        }
    }
    float b0 = db[dg * 2], b1 = db[dg * 2 + 1];
    #pragma unroll
    for (int bi = 0; bi < 4; bi++) {
        int b = bg * 4 + bi;
        size_t base = (size_t)b * NT * NDS + (size_t)t * NDS + dg * 2;
        out[base]     = tanhf(acc[bi][0] + b0);
        out[base + 1] = tanhf(acc[bi][1] + b1);
    }
}

#define DENSE_SMEM ((NH * NB + NH * NDS) * 4)

extern "C" void kernel_launch(void* const* d_in, const int* in_sizes, int n_in,
                              void* d_out, int out_size) {
    const float* x    = (const float*)d_in[0];
    const float* wk   = (const float*)d_in[1];
    const float* wr   = (const float*)d_in[2];
    const float* bias = (const float*)d_in[3];
    const float* dw   = (const float*)d_in[4];
    const float* db   = (const float*)d_in[5];
    float* out   = (float*)d_out;
    float* out_h = out + (size_t)NB * NT * NDS;
    float* out_c = out_h + (size_t)NB * NH;

    cudaFuncSetAttribute(xw_kernel,
                         cudaFuncAttributeMaxDynamicSharedMemorySize, XW_SMEM);
    cudaFuncSetAttribute(lstm_kernel,
                         cudaFuncAttributeMaxDynamicSharedMemorySize, LSTM_SMEM);
    cudaFuncSetAttribute(dense_kernel,
                         cudaFuncAttributeMaxDynamicSharedMemorySize, DENSE_SMEM);

    init_kernel<<<64, 256>>>();                          // 0
    wbf_kernel<<<2 * NG4, ND>>>(wk);                     // 1
    xw_kernel<<<NT, 256, XW_SMEM>>>(x, bias);            // 2
    lstm_kernel<<<G, TPB, LSTM_SMEM>>>(wr, out_h, out_c);// 3  <- profiled slot
    dense_kernel<<<NT, DTPB, DENSE_SMEM>>>(dw, db, out); // 4
}

// round 12
// speedup vs baseline: 1.8858x; 1.1098x over previous
#include <cuda_runtime.h>
#include <cuda_bf16.h>
#include <cuda_fp16.h>
#include <cstdint>
#include <math.h>

// ---------------- problem dims ----------------
#define NB 64
#define NT 512
#define ND 128
#define NH 512
#define NDS 32
#define NG4 (4 * NH)   // 2048

// ---------------- LSTM config ----------------
#define G 128          // persistent CTAs, 1/SM
#define TPB 256        // 8 warps
#define JPC 4          // hidden units per CTA -> 16 true z-cols -> m=32 (W hi/lo pair)
// SMEM layout (bytes)
#define H_OFF 0                    // h [4 chunks][64 rows][256B] = 65536
#define WS_OFF 65536               // W' staging [32][1024B] = 32768 (zb aliases)
#define MB_OFF 98304               // 4 mbarriers
#define LSTM_SMEM 98368

__device__ __forceinline__ uint32_t smem_u32(const void* p) {
    uint32_t a;
    asm("{ .reg .u64 t; cvta.to.shared.u64 t, %1; cvt.u32.u64 %0, t; }" : "=r"(a) : "l"(p));
    return a;
}
__device__ __forceinline__ uint16_t bf16_bits(float f) {
    return __bfloat16_as_ushort(__float2bfloat16(f));
}
__device__ __forceinline__ float bf16_val(float f) {
    return __bfloat162float(__float2bfloat16(f));
}
__device__ __forceinline__ uint16_t bf16_lo(float f) {
    return bf16_bits(f - bf16_val(f));
}
// fast gate nonlinearities (MUFU-based)
__device__ __forceinline__ float fsig(float x) { return 1.f / (1.f + __expf(-x)); }
__device__ __forceinline__ float ftanh(float x) {
    float ax = fabsf(x);
    float e = __expf(-2.f * ax);
    float r = (1.f - e) / (1.f + e);
    return copysignf(r, x);
}

__device__ __forceinline__ uint4 pack_hi8(float4 a, float4 b) {
    uint4 r;
    r.x = (uint32_t)bf16_bits(a.x) | ((uint32_t)bf16_bits(a.y) << 16);
    r.y = (uint32_t)bf16_bits(a.z) | ((uint32_t)bf16_bits(a.w) << 16);
    r.z = (uint32_t)bf16_bits(b.x) | ((uint32_t)bf16_bits(b.y) << 16);
    r.w = (uint32_t)bf16_bits(b.z) | ((uint32_t)bf16_bits(b.w) << 16);
    return r;
}
__device__ __forceinline__ uint4 pack_lo8(float4 a, float4 b) {
    uint4 r;
    r.x = (uint32_t)bf16_lo(a.x) | ((uint32_t)bf16_lo(a.y) << 16);
    r.y = (uint32_t)bf16_lo(a.z) | ((uint32_t)bf16_lo(a.w) << 16);
    r.z = (uint32_t)bf16_lo(b.x) | ((uint32_t)bf16_lo(b.y) << 16);
    r.w = (uint32_t)bf16_lo(b.z) | ((uint32_t)bf16_lo(b.w) << 16);
    return r;
}

#define LDSM_X4(r0, r1, r2, r3, addr) \
    asm volatile("ldmatrix.sync.aligned.m8n8.x4.shared.b16 {%0,%1,%2,%3}, [%4];" \
        : "=r"(r0), "=r"(r1), "=r"(r2), "=r"(r3) : "r"(addr))

#define MMA_BF16(c, a0, a1, a2, a3, b0, b1) \
    asm volatile("mma.sync.aligned.m16n8k16.row.col.f32.bf16.bf16.f32 " \
        "{%0,%1,%2,%3}, {%4,%5,%6,%7}, {%8,%9}, {%0,%1,%2,%3};" \
        : "+f"((c)[0]), "+f"((c)[1]), "+f"((c)[2]), "+f"((c)[3]) \
        : "r"(a0), "r"(a1), "r"(a2), "r"(a3), "r"(b0), "r"(b1))

#define MMA_FP16(c, a0, a1, a2, a3, b0, b1) \
    asm volatile("mma.sync.aligned.m16n8k16.row.col.f32.f16.f16.f32 " \
        "{%0,%1,%2,%3}, {%4,%5,%6,%7}, {%8,%9}, {%0,%1,%2,%3};" \
        : "+f"((c)[0]), "+f"((c)[1]), "+f"((c)[2]), "+f"((c)[3]) \
        : "r"(a0), "r"(a1), "r"(a2), "r"(a3), "r"(b0), "r"(b1))

#define CP16(dst, src) \
    asm volatile("cp.async.cg.shared.global [%0], [%1], 16;" :: "r"(dst), "l"(src))
#define CP_COMMIT() asm volatile("cp.async.commit_group;" ::: "memory")
#define CP_WAIT(n)  asm volatile("cp.async.wait_group %0;" :: "n"(n) : "memory")
#define MBARRIER_INIT(mbar, cnt) \
    asm volatile("mbarrier.init.shared.b64 [%0], %1;" :: "r"((uint32_t)(mbar)), "r"((uint32_t)(cnt)) : "memory")
#define MBARRIER_EXPECT_TX(mbar, bytes) \
    asm volatile("mbarrier.arrive.expect_tx.shared.b64 _, [%0], %1;" \
                 :: "r"((uint32_t)(mbar)), "r"((uint32_t)(bytes)) : "memory")
#define BULK_G2S(dst, src, bytes, mbar) \
    asm volatile("cp.async.bulk.shared::cta.global.mbarrier::complete_tx::bytes " \
                 "[%0], [%1], %2, [%3];" \
                 :: "r"((uint32_t)(dst)), "l"(src), "r"((uint32_t)(bytes)), \
                    "r"((uint32_t)(mbar)) : "memory")
#define MBARRIER_WAIT_PARITY(mbar, par) do { \
    uint32_t _m = (uint32_t)(mbar); uint32_t _p = (uint32_t)(par); uint32_t _d; \
    asm volatile("{\n\t.reg .pred p;\n\t" \
        "mbarrier.try_wait.parity.acquire.cta.shared::cta.b64 p, [%1], %2;\n\t" \
        "selp.b32 %0, 1, 0, p;\n\t}" : "=r"(_d) : "r"(_m), "r"(_p) : "memory"); \
    if (!_d) { \
        asm volatile("{\n\t.reg .pred P1;\n\t" \
            "WL_%=:\n\t" \
            "mbarrier.try_wait.parity.acquire.cta.shared::cta.b64 P1, [%0], %1, 0x989680;\n\t" \
            "@P1 bra.uni WD_%=;\n\t" \
            "bra.uni WL_%=;\n\t" \
            "WD_%=:\n\t}" :: "r"(_m), "r"(_p) : "memory"); \
    } } while (0)

// ---------------- global scratch ----------------
// h (fp16) in the exact swizzled SMEM image: [buf][chunk(k128)][row=batch][256B]
__device__ __align__(128) uint8_t g_hb[2][4][64][256];
__device__ __nv_bfloat16 g_wt[2 * NG4][ND];     // wk transposed hi/lo (bf16, xw path)
__device__ float g_xw[NT][NG4][NB];             // x@Wk + bias
__device__ float g_hs[NT][NH][NB];              // hidden states for dense
__device__ unsigned int g_cbar[4 * 32];         // per-chunk monotonic counters

__global__ void init_kernel() {
    int idx = blockIdx.x * blockDim.x + threadIdx.x;
    if (idx < 4 * 32) g_cbar[idx] = 0u;
    uint32_t* p = reinterpret_cast<uint32_t*>(&g_hb[0][0][0][0]);
    for (int i = idx; i < (int)(sizeof(g_hb) / 4); i += gridDim.x * blockDim.x)
        p[i] = 0u;
}

// ---- one-time: transpose + bf16 hi/lo split of wk ----
__global__ void wbf_kernel(const float* __restrict__ wk) {
    int n = blockIdx.x;
    int k = threadIdx.x;
    float w = wk[(size_t)k * NG4 + (n & (NG4 - 1))];
    g_wt[n][k] = (n < NG4) ? __ushort_as_bfloat16(bf16_bits(w))
                           : __ushort_as_bfloat16(bf16_lo(w));
}

// =====================================================================
// XW kernel (proven): g_xw[t][col][b] = x@wk + bias
// =====================================================================
#define XA_OFF 0
#define XB_OFF 32768
#define XZ_OFF 65536
#define XW_SMEM 132096

__global__ void __launch_bounds__(256, 1) xw_kernel(
    const float* __restrict__ x, const float* __restrict__ bias)
{
    extern __shared__ char smem[];
    const uint32_t sbu = smem_u32(smem);
    float* zb = reinterpret_cast<float*>(smem + XZ_OFF);
    const int tid = threadIdx.x, wid = tid >> 5, lane = tid & 31;
    const int t = blockIdx.x;
    const int s7 = lane & 7;

    for (int i = tid; i < 64 * 16; i += 256) {
        int b = i >> 4, cs = i & 15;
        const float4* xp = reinterpret_cast<const float4*>(
            x + ((size_t)b * NT + t) * ND + cs * 8);
        float4 x0 = xp[0], x1 = xp[1];
        *reinterpret_cast<uint4*>(smem + XA_OFF + b * 256 + ((cs ^ (b & 7)) << 4))
            = pack_hi8(x0, x1);
        int rl = b + 64;
        *reinterpret_cast<uint4*>(smem + XA_OFF + rl * 256 + ((cs ^ (rl & 7)) << 4))
            = pack_lo8(x0, x1);
    }
    __syncthreads();

    const int mslice = wid & 3, whalf = wid >> 2;
    uint32_t ar[8][2][4];
    {
        int row8 = ((lane >> 3) & 1) * 8 + s7;
        int acb = lane >> 4;
        #pragma unroll
        for (int ks = 0; ks < 8; ks++)
            #pragma unroll
            for (int mf = 0; mf < 2; mf++) {
                int row = mslice * 32 + mf * 16 + row8;
                uint32_t addr = sbu + XA_OFF + row * 256 +
                    (((ks * 2 + acb) ^ (row & 7)) << 4);
                LDSM_X4(ar[ks][mf][0], ar[ks][mf][1], ar[ks][mf][2], ar[ks][mf][3], addr);
            }
    }

    const int browl = ((lane >> 4) << 3) + s7;
    const int bcb = (lane >> 3) & 1;

    for (int cb = 0; cb < 32; cb++) {
        #pragma unroll
        for (int it = 0; it < 8; it++) {
            int i = it * 256 + tid;
            int row = i >> 4, cpi = i & 15;
            const __nv_bfloat16* src = (row < 64)
                ? &g_wt[cb * 64 + row][cpi * 8]
                : &g_wt[NG4 + cb * 64 + (row - 64)][cpi * 8];
            uint32_t dst = sbu + XB_OFF + row * 256 + ((cpi ^ (row & 7)) << 4);
            CP16(dst, src);
        }
        CP_COMMIT();
        CP_WAIT(0);
        __syncthreads();

        float acc[2][8][4];
        #pragma unroll
        for (int mf = 0; mf < 2; mf++)
            #pragma unroll
            for (int nf = 0; nf < 8; nf++)
                #pragma unroll
                for (int q = 0; q < 4; q++) acc[mf][nf][q] = 0.f;

        #pragma unroll
        for (int ks = 0; ks < 8; ks++) {
            #pragma unroll
            for (int q = 0; q < 4; q++) {
                int rowb = whalf * 64 + q * 16 + browl;
                uint32_t baddr = sbu + XB_OFF + rowb * 256 +
                    (((ks * 2 + bcb) ^ s7) << 4);
                uint32_t b0, b1, b2, b3;
                LDSM_X4(b0, b1, b2, b3, baddr);
                #pragma unroll
                for (int mf = 0; mf < 2; mf++) {
                    MMA_BF16(acc[mf][2 * q],     ar[ks][mf][0], ar[ks][mf][1],
                             ar[ks][mf][2], ar[ks][mf][3], b0, b1);
                    MMA_BF16(acc[mf][2 * q + 1], ar[ks][mf][0], ar[ks][mf][1],
                             ar[ks][mf][2], ar[ks][mf][3], b2, b3);
                }
            }
        }

        #pragma unroll
        for (int mf = 0; mf < 2; mf++)
            #pragma unroll
            for (int nf = 0; nf < 8; nf++) {
                int m = mslice * 32 + mf * 16 + (lane >> 2);
                int c = nf * 8 + 2 * (lane & 3);
                float* zp = zb + (size_t)(whalf * 128 + m) * 65 + c;
                zp[0] = acc[mf][nf][0];
                zp[1] = acc[mf][nf][1];
                zp[8 * 65] = acc[mf][nf][2];
                zp[8 * 65 + 1] = acc[mf][nf][3];
            }
        __syncthreads();

        for (int i = tid; i < 64 * 64; i += 256) {
            int b = i & 63, c = i >> 6;
            float z = zb[(size_t)b * 65 + c] + zb[(size_t)(128 + b) * 65 + c]
                    + zb[(size_t)(b + 64) * 65 + c] + zb[(size_t)(128 + b + 64) * 65 + c]
                    + bias[cb * 64 + c];
            g_xw[t][cb * 64 + c][b] = z;
        }
        __syncthreads();
    }
}

// =====================================================================
// Persistent LSTM — fp16 scheme. z = (Whi + Wlo)·h_fp16 = W·h_fp16 exactly.
// 8 warps = 2 m-halves (Whi/Wlo, m16) x 4 n-slices (n16 of 64 batches).
// h: ONE fp16 array, 4 k-chunks of 16KB via cp.async.bulk.
// =====================================================================
__global__ void __launch_bounds__(TPB, 1) lstm_kernel(
    const float* __restrict__ wr,
    float* __restrict__ out_h, float* __restrict__ out_c)
{
    extern __shared__ char smem[];
    const uint32_t sbu = smem_u32(smem);
    float* zb = reinterpret_cast<float*>(smem + WS_OFF);   // [64][33] aliases W staging

    const int tid = threadIdx.x;
    const int wid = tid >> 5, lane = tid & 31;
    const int j0 = blockIdx.x * JPC;
    const int s7 = lane & 7;
    const int mhalf = wid & 1;          // 0 = Whi, 1 = Wlo
    const int nslice = wid >> 1;        // 0..3 -> batch rows [16*nslice, +16)
    const int mychunk = blockIdx.x >> 5;

    if (tid == 0) {
        #pragma unroll
        for (int c = 0; c < 4; c++) MBARRIER_INIT(sbu + MB_OFF + 8 * c, 1);
    }

    // ---- W' staging (fp16): rows m 0-15 = Whi of col(gate*4+jj), 16-31 = Wlo ----
    for (int i = tid; i < 32 * NH; i += TPB) {
        int m = i & 31, k = i >> 5;
        int c = m & 15, gate = c >> 2, jj = c & 3;
        float w = wr[(size_t)k * NG4 + gate * NH + j0 + jj];
        __half whi = __float2half(w);
        uint16_t bv = (m < 16) ? __half_as_ushort(whi)
                               : __half_as_ushort(__float2half(w - __half2float(whi)));
        *reinterpret_cast<uint16_t*>(smem + WS_OFF + m * 1024 +
            ((((k >> 3) ^ (m & 7)) << 4) | ((k & 7) << 1))) = bv;
    }
    __syncthreads();

    // ---- a-frags: full k=512, this warp's m16 (Whi or Wlo) ----
    uint32_t ar[32][4];
    {
        int row = mhalf * 16 + ((lane >> 3) & 1) * 8 + s7;
        int acb = lane >> 4;
        uint32_t rbase = sbu + WS_OFF + row * 1024;
        #pragma unroll
        for (int ks = 0; ks < 32; ks++) {
            int chunk = ks * 2 + acb;
            LDSM_X4(ar[ks][0], ar[ks][1], ar[ks][2], ar[ks][3],
                    rbase + ((chunk ^ (row & 7)) << 4));
        }
    }
    __syncthreads();   // staging free; zb reuses it

    const int gb = tid & 63;
    const int gj = (tid >> 6) & 3;
    float c_state = 0.f;

    const int browl = ((lane >> 4) << 3) + s7;
    const int bcb = (lane >> 3) & 1;
    const int rowsl = nslice * 16 + browl;

    // producer h-write address (pre-swizzled fp16 image)
    const int jrow = j0 + gj;
    const int kq = jrow & 127;               // k index within chunk
    const size_t poff = (size_t)(jrow >> 7) * 16384 + (size_t)gb * 256 +
                        (((kq >> 3) ^ (gb & 7)) << 4) + (kq & 7) * 2;

    for (int t = 0; t < NT; t++) {
        // prefetch xw (DRAM; consumed at gates)
        float xwv[4];
        #pragma unroll
        for (int g = 0; g < 4; g++)
            xwv[g] = __ldcg(&g_xw[t][g * NH + j0 + gj][gb]);

        const int buf = t & 1;
        // ---- tid0: per chunk poll counter, then ONE 16KB bulk copy ----
        if (tid == 0) {
            const uint8_t* hsrc = &g_hb[buf][0][0][0];
            #pragma unroll
            for (int ch = 0; ch < 4; ch++) {
                const unsigned int tgt = 32u * (unsigned int)t;
                const unsigned int* cp = &g_cbar[ch * 32];
                unsigned int cur;
                do {
                    asm volatile("ld.global.acquire.gpu.u32 %0, [%1];"
                                 : "=r"(cur) : "l"(cp));
                } while (cur < tgt);
                MBARRIER_EXPECT_TX(sbu + MB_OFF + 8 * ch, 16384);
                BULK_G2S(sbu + H_OFF + ch * 16384, hsrc + (size_t)ch * 16384,
                         16384, sbu + MB_OFF + 8 * ch);
            }
        }

        float acc[2][4];
        #pragma unroll
        for (int nf = 0; nf < 2; nf++)
            #pragma unroll
            for (int q = 0; q < 4; q++) acc[nf][q] = 0.f;

        // ---- chunk-ordered MMA: per ks one LDSM.x4 (n16) + 2 MMA ----
        #pragma unroll
        for (int c = 0; c < 4; c++) {
            MBARRIER_WAIT_PARITY(sbu + MB_OFF + 8 * c, t & 1);
            uint32_t base0 = sbu + H_OFF + c * 16384 + rowsl * 256;
            #pragma unroll
            for (int kk = 0; kk < 8; kk++) {
                int ks = c * 8 + kk;
                uint32_t off = (((kk * 2 + bcb) ^ s7) << 4);
                uint32_t b00, b01, b10, b11;
                LDSM_X4(b00, b01, b10, b11, base0 + off);
                MMA_FP16(acc[0], ar[ks][0], ar[ks][1], ar[ks][2], ar[ks][3], b00, b01);
                MMA_FP16(acc[1], ar[ks][0], ar[ks][1], ar[ks][2], ar[ks][3], b10, b11);
            }
        }

        // ---- epilogue: zb[n=batch][m=0..31] ----
        {
            int m = mhalf * 16 + (lane >> 2);
            #pragma unroll
            for (int nf = 0; nf < 2; nf++) {
                int n = nslice * 16 + nf * 8 + 2 * (lane & 3);
                zb[(size_t)n * 33 + m]           = acc[nf][0];
                zb[(size_t)(n + 1) * 33 + m]     = acc[nf][1];
                zb[(size_t)n * 33 + m + 8]       = acc[nf][2];
                zb[(size_t)(n + 1) * 33 + m + 8] = acc[nf][3];
            }
        }
        __syncthreads();

        // ---- gates: z = xw + Whi·h + Wlo·h ----
        {
            float z[4];
            #pragma unroll
            for (int g = 0; g < 4; g++) {
                int c = g * 4 + gj;
                z[g] = xwv[g] + zb[(size_t)gb * 33 + c] + zb[(size_t)gb * 33 + c + 16];
            }
            float ig = fsig(z[0]);
            float fg = fsig(z[1]);
            float gv = ftanh(z[2]);
            float og = fsig(z[3]);
            c_state = fg * c_state + ig * gv;
            float hv = og * ftanh(c_state);
            uint8_t* hdst = &g_hb[(t + 1) & 1][0][0][0];
            *reinterpret_cast<uint16_t*>(hdst + poff) =
                __half_as_ushort(__float2half(hv));
            g_hs[t][jrow][gb] = hv;
            if (t == NT - 1) {
                out_h[(size_t)gb * NH + jrow] = hv;
                out_c[(size_t)gb * NH + jrow] = c_state;
            }
        }
        __syncthreads();

        // ---- producer publish: tid0 cumulative fence + one atomic ----
        if (t < NT - 1 && tid == 0) {
            __threadfence();
            atomicAdd(&g_cbar[mychunk * 32], 1u);
        }
    }
}

// ---------------- Dense(32, tanh) over all timesteps ----------------
#define DTPB 256
__global__ void __launch_bounds__(DTPB, 1) dense_kernel(
    const float* __restrict__ dw, const float* __restrict__ db,
    float* __restrict__ out)
{
    extern __shared__ float smemf[];
    float* hsm = smemf;
    float* wsm = smemf + NH * NB;
    int t = blockIdx.x, tid = threadIdx.x;
    {
        const float4* src = reinterpret_cast<const float4*>(&g_hs[t][0][0]);
        float4* dst = reinterpret_cast<float4*>(hsm);
        for (int i = tid; i < NH * NB / 4; i += DTPB) dst[i] = src[i];
        const float4* ws = reinterpret_cast<const float4*>(dw);
        float4* wd = reinterpret_cast<float4*>(wsm);
        for (int i = tid; i < NH * NDS / 4; i += DTPB) wd[i] = ws[i];
    }
    __syncthreads();

    int bg = tid & 15, dg = tid >> 4;
    float acc[4][2];
    #pragma unroll
    for (int bi = 0; bi < 4; bi++) { acc[bi][0] = 0.f; acc[bi][1] = 0.f; }
    #pragma unroll 4
    for (int k = 0; k < NH; k++) {
        float4 hv = *reinterpret_cast<const float4*>(&hsm[k * NB + bg * 4]);
        float2 wv = *reinterpret_cast<const float2*>(&wsm[k * NDS + dg * 2]);
        float hvv[4] = {hv.x, hv.y, hv.z, hv.w};
        #pragma unroll
        for (int bi = 0; bi < 4; bi++) {
            acc[bi][0] += hvv[bi] * wv.x;
            acc[bi][1] += hvv[bi] * wv.y;
        }
    }
    float b0 = db[dg * 2], b1 = db[dg * 2 + 1];
    #pragma unroll
    for (int bi = 0; bi < 4; bi++) {
        int b = bg * 4 + bi;
        size_t base = (size_t)b * NT * NDS + (size_t)t * NDS + dg * 2;
        out[base]     = tanhf(acc[bi][0] + b0);
        out[base + 1] = tanhf(acc[bi][1] + b1);
    }
}

#define DENSE_SMEM ((NH * NB + NH * NDS) * 4)

extern "C" void kernel_launch(void* const* d_in, const int* in_sizes, int n_in,
                              void* d_out, int out_size) {
    const float* x    = (const float*)d_in[0];
    const float* wk   = (const float*)d_in[1];
    const float* wr   = (const float*)d_in[2];
    const float* bias = (const float*)d_in[3];
    const float* dw   = (const float*)d_in[4];
    const float* db   = (const float*)d_in[5];
    float* out   = (float*)d_out;
    float* out_h = out + (size_t)NB * NT * NDS;
    float* out_c = out_h + (size_t)NB * NH;

    cudaFuncSetAttribute(xw_kernel,
                         cudaFuncAttributeMaxDynamicSharedMemorySize, XW_SMEM);
    cudaFuncSetAttribute(lstm_kernel,
                         cudaFuncAttributeMaxDynamicSharedMemorySize, LSTM_SMEM);
    cudaFuncSetAttribute(dense_kernel,
                         cudaFuncAttributeMaxDynamicSharedMemorySize, DENSE_SMEM);

    init_kernel<<<64, 256>>>();                          // 0
    wbf_kernel<<<2 * NG4, ND>>>(wk);                     // 1
    xw_kernel<<<NT, 256, XW_SMEM>>>(x, bias);            // 2
    lstm_kernel<<<G, TPB, LSTM_SMEM>>>(wr, out_h, out_c);// 3  <- profiled slot
    dense_kernel<<<NT, DTPB, DENSE_SMEM>>>(dw, db, out); // 4
}

// round 13
// speedup vs baseline: 2.7191x; 1.4419x over previous
#include <cuda_runtime.h>
#include <cuda_bf16.h>
#include <cuda_fp16.h>
#include <cstdint>
#include <math.h>

// ---------------- problem dims ----------------
#define NB 64
#define NT 512
#define ND 128
#define NH 512
#define NDS 32
#define NG4 (4 * NH)   // 2048

// ---------------- LSTM config ----------------
#define G 128          // persistent CTAs, 1/SM
#define TPB 256        // 8 warps
#define JPC 4          // hidden units per CTA -> 16 true z-cols (m=16, fp16 W)
// SMEM layout (bytes)
#define H_OFF 0                    // h [4 chunks][64 rows][256B] = 65536
#define WS_OFF 65536               // W' staging [16][1024B] = 16384
#define MB_OFF 81920               // 4 mbarriers
#define LSTM_SMEM 81984

__device__ __forceinline__ uint32_t smem_u32(const void* p) {
    uint32_t a;
    asm("{ .reg .u64 t; cvta.to.shared.u64 t, %1; cvt.u32.u64 %0, t; }" : "=r"(a) : "l"(p));
    return a;
}
__device__ __forceinline__ uint16_t bf16_bits(float f) {
    return __bfloat16_as_ushort(__float2bfloat16(f));
}
__device__ __forceinline__ float bf16_val(float f) {
    return __bfloat162float(__float2bfloat16(f));
}
__device__ __forceinline__ uint16_t bf16_lo(float f) {
    return bf16_bits(f - bf16_val(f));
}
// fast gate nonlinearities (MUFU-based)
__device__ __forceinline__ float fsig(float x) { return 1.f / (1.f + __expf(-x)); }
__device__ __forceinline__ float ftanh(float x) {
    float ax = fabsf(x);
    float e = __expf(-2.f * ax);
    float r = (1.f - e) / (1.f + e);
    return copysignf(r, x);
}

__device__ __forceinline__ uint4 pack_hi8(float4 a, float4 b) {
    uint4 r;
    r.x = (uint32_t)bf16_bits(a.x) | ((uint32_t)bf16_bits(a.y) << 16);
    r.y = (uint32_t)bf16_bits(a.z) | ((uint32_t)bf16_bits(a.w) << 16);
    r.z = (uint32_t)bf16_bits(b.x) | ((uint32_t)bf16_bits(b.y) << 16);
    r.w = (uint32_t)bf16_bits(b.z) | ((uint32_t)bf16_bits(b.w) << 16);
    return r;
}
__device__ __forceinline__ uint4 pack_lo8(float4 a, float4 b) {
    uint4 r;
    r.x = (uint32_t)bf16_lo(a.x) | ((uint32_t)bf16_lo(a.y) << 16);
    r.y = (uint32_t)bf16_lo(a.z) | ((uint32_t)bf16_lo(a.w) << 16);
    r.z = (uint32_t)bf16_lo(b.x) | ((uint32_t)bf16_lo(b.y) << 16);
    r.w = (uint32_t)bf16_lo(b.z) | ((uint32_t)bf16_lo(b.w) << 16);
    return r;
}

#define LDSM_X4(r0, r1, r2, r3, addr) \
    asm volatile("ldmatrix.sync.aligned.m8n8.x4.shared.b16 {%0,%1,%2,%3}, [%4];" \
        : "=r"(r0), "=r"(r1), "=r"(r2), "=r"(r3) : "r"(addr))
#define LDSM_X2(r0, r1, addr) \
    asm volatile("ldmatrix.sync.aligned.m8n8.x2.shared.b16 {%0,%1}, [%2];" \
        : "=r"(r0), "=r"(r1) : "r"(addr))

#define MMA_BF16(c, a0, a1, a2, a3, b0, b1) \
    asm volatile("mma.sync.aligned.m16n8k16.row.col.f32.bf16.bf16.f32 " \
        "{%0,%1,%2,%3}, {%4,%5,%6,%7}, {%8,%9}, {%0,%1,%2,%3};" \
        : "+f"((c)[0]), "+f"((c)[1]), "+f"((c)[2]), "+f"((c)[3]) \
        : "r"(a0), "r"(a1), "r"(a2), "r"(a3), "r"(b0), "r"(b1))

#define MMA_FP16(c, a0, a1, a2, a3, b0, b1) \
    asm volatile("mma.sync.aligned.m16n8k16.row.col.f32.f16.f16.f32 " \
        "{%0,%1,%2,%3}, {%4,%5,%6,%7}, {%8,%9}, {%0,%1,%2,%3};" \
        : "+f"((c)[0]), "+f"((c)[1]), "+f"((c)[2]), "+f"((c)[3]) \
        : "r"(a0), "r"(a1), "r"(a2), "r"(a3), "r"(b0), "r"(b1))

#define CP16(dst, src) \
    asm volatile("cp.async.cg.shared.global [%0], [%1], 16;" :: "r"(dst), "l"(src))
#define CP_COMMIT() asm volatile("cp.async.commit_group;" ::: "memory")
#define CP_WAIT(n)  asm volatile("cp.async.wait_group %0;" :: "n"(n) : "memory")
#define MBARRIER_INIT(mbar, cnt) \
    asm volatile("mbarrier.init.shared.b64 [%0], %1;" :: "r"((uint32_t)(mbar)), "r"((uint32_t)(cnt)) : "memory")
#define MBARRIER_EXPECT_TX(mbar, bytes) \
    asm volatile("mbarrier.arrive.expect_tx.shared.b64 _, [%0], %1;" \
                 :: "r"((uint32_t)(mbar)), "r"((uint32_t)(bytes)) : "memory")
#define BULK_G2S(dst, src, bytes, mbar) \
    asm volatile("cp.async.bulk.shared::cta.global.mbarrier::complete_tx::bytes " \
                 "[%0], [%1], %2, [%3];" \
                 :: "r"((uint32_t)(dst)), "l"(src), "r"((uint32_t)(bytes)), \
                    "r"((uint32_t)(mbar)) : "memory")
#define MBARRIER_WAIT_PARITY(mbar, par) do { \
    uint32_t _m = (uint32_t)(mbar); uint32_t _p = (uint32_t)(par); uint32_t _d; \
    asm volatile("{\n\t.reg .pred p;\n\t" \
        "mbarrier.try_wait.parity.acquire.cta.shared::cta.b64 p, [%1], %2;\n\t" \
        "selp.b32 %0, 1, 0, p;\n\t}" : "=r"(_d) : "r"(_m), "r"(_p) : "memory"); \
    if (!_d) { \
        asm volatile("{\n\t.reg .pred P1;\n\t" \
            "WL_%=:\n\t" \
            "mbarrier.try_wait.parity.acquire.cta.shared::cta.b64 P1, [%0], %1, 0x989680;\n\t" \
            "@P1 bra.uni WD_%=;\n\t" \
            "bra.uni WL_%=;\n\t" \
            "WD_%=:\n\t}" :: "r"(_m), "r"(_p) : "memory"); \
    } } while (0)

// ---------------- global scratch ----------------
// h (fp16) in the exact swizzled SMEM image: [buf][chunk(k128)][row=batch][256B]
__device__ __align__(128) uint8_t g_hb[2][4][64][256];
__device__ __nv_bfloat16 g_wt[2 * NG4][ND];     // wk transposed hi/lo (bf16, xw path)
__device__ float g_xw[NT][NG4][NB];             // x@Wk + bias
__device__ float g_hs[NT][NH][NB];              // hidden states for dense
__device__ unsigned int g_cbar[4 * 32];         // per-chunk monotonic counters

__global__ void init_kernel() {
    int idx = blockIdx.x * blockDim.x + threadIdx.x;
    if (idx < 4 * 32) g_cbar[idx] = 0u;
    uint32_t* p = reinterpret_cast<uint32_t*>(&g_hb[0][0][0][0]);
    for (int i = idx; i < (int)(sizeof(g_hb) / 4); i += gridDim.x * blockDim.x)
        p[i] = 0u;
}

// ---- one-time: transpose + bf16 hi/lo split of wk ----
__global__ void wbf_kernel(const float* __restrict__ wk) {
    int n = blockIdx.x;
    int k = threadIdx.x;
    float w = wk[(size_t)k * NG4 + (n & (NG4 - 1))];
    g_wt[n][k] = (n < NG4) ? __ushort_as_bfloat16(bf16_bits(w))
                           : __ushort_as_bfloat16(bf16_lo(w));
}

// =====================================================================
// XW kernel (proven): g_xw[t][col][b] = x@wk + bias
// =====================================================================
#define XA_OFF 0
#define XB_OFF 32768
#define XZ_OFF 65536
#define XW_SMEM 132096

__global__ void __launch_bounds__(256, 1) xw_kernel(
    const float* __restrict__ x, const float* __restrict__ bias)
{
    extern __shared__ char smem[];
    const uint32_t sbu = smem_u32(smem);
    float* zb = reinterpret_cast<float*>(smem + XZ_OFF);
    const int tid = threadIdx.x, wid = tid >> 5, lane = tid & 31;
    const int t = blockIdx.x;
    const int s7 = lane & 7;

    for (int i = tid; i < 64 * 16; i += 256) {
        int b = i >> 4, cs = i & 15;
        const float4* xp = reinterpret_cast<const float4*>(
            x + ((size_t)b * NT + t) * ND + cs * 8);
        float4 x0 = xp[0], x1 = xp[1];
        *reinterpret_cast<uint4*>(smem + XA_OFF + b * 256 + ((cs ^ (b & 7)) << 4))
            = pack_hi8(x0, x1);
        int rl = b + 64;
        *reinterpret_cast<uint4*>(smem + XA_OFF + rl * 256 + ((cs ^ (rl & 7)) << 4))
            = pack_lo8(x0, x1);
    }
    __syncthreads();

    const int mslice = wid & 3, whalf = wid >> 2;
    uint32_t ar[8][2][4];
    {
        int row8 = ((lane >> 3) & 1) * 8 + s7;
        int acb = lane >> 4;
        #pragma unroll
        for (int ks = 0; ks < 8; ks++)
            #pragma unroll
            for (int mf = 0; mf < 2; mf++) {
                int row = mslice * 32 + mf * 16 + row8;
                uint32_t addr = sbu + XA_OFF + row * 256 +
                    (((ks * 2 + acb) ^ (row & 7)) << 4);
                LDSM_X4(ar[ks][mf][0], ar[ks][mf][1], ar[ks][mf][2], ar[ks][mf][3], addr);
            }
    }

    const int browl = ((lane >> 4) << 3) + s7;
    const int bcb = (lane >> 3) & 1;

    for (int cb = 0; cb < 32; cb++) {
        #pragma unroll
        for (int it = 0; it < 8; it++) {
            int i = it * 256 + tid;
            int row = i >> 4, cpi = i & 15;
            const __nv_bfloat16* src = (row < 64)
                ? &g_wt[cb * 64 + row][cpi * 8]
                : &g_wt[NG4 + cb * 64 + (row - 64)][cpi * 8];
            uint32_t dst = sbu + XB_OFF + row * 256 + ((cpi ^ (row & 7)) << 4);
            CP16(dst, src);
        }
        CP_COMMIT();
        CP_WAIT(0);
        __syncthreads();

        float acc[2][8][4];
        #pragma unroll
        for (int mf = 0; mf < 2; mf++)
            #pragma unroll
            for (int nf = 0; nf < 8; nf++)
                #pragma unroll
                for (int q = 0; q < 4; q++) acc[mf][nf][q] = 0.f;

        #pragma unroll
        for (int ks = 0; ks < 8; ks++) {
            #pragma unroll
            for (int q = 0; q < 4; q++) {
                int rowb = whalf * 64 + q * 16 + browl;
                uint32_t baddr = sbu + XB_OFF + rowb * 256 +
                    (((ks * 2 + bcb) ^ s7) << 4);
                uint32_t b0, b1, b2, b3;
                LDSM_X4(b0, b1, b2, b3, baddr);
                #pragma unroll
                for (int mf = 0; mf < 2; mf++) {
                    MMA_BF16(acc[mf][2 * q],     ar[ks][mf][0], ar[ks][mf][1],
                             ar[ks][mf][2], ar[ks][mf][3], b0, b1);
                    MMA_BF16(acc[mf][2 * q + 1], ar[ks][mf][0], ar[ks][mf][1],
                             ar[ks][mf][2], ar[ks][mf][3], b2, b3);
                }
            }
        }

        #pragma unroll
        for (int mf = 0; mf < 2; mf++)
            #pragma unroll
            for (int nf = 0; nf < 8; nf++) {
                int m = mslice * 32 + mf * 16 + (lane >> 2);
                int c = nf * 8 + 2 * (lane & 3);
                float* zp = zb + (size_t)(whalf * 128 + m) * 65 + c;
                zp[0] = acc[mf][nf][0];
                zp[1] = acc[mf][nf][1];
                zp[8 * 65] = acc[mf][nf][2];
                zp[8 * 65 + 1] = acc[mf][nf][3];
            }
        __syncthreads();

        for (int i = tid; i < 64 * 64; i += 256) {
            int b = i & 63, c = i >> 6;
            float z = zb[(size_t)b * 65 + c] + zb[(size_t)(128 + b) * 65 + c]
                    + zb[(size_t)(b + 64) * 65 + c] + zb[(size_t)(128 + b + 64) * 65 + c]
                    + bias[cb * 64 + c];
            g_xw[t][cb * 64 + c][b] = z;
        }
        __syncthreads();
    }
}

// =====================================================================
// Persistent LSTM — fp16 W (m16), 8 warps x (m16 x n8). Each warp owns
// 8 batches x 16 z-cols -> gates fully in-warp via shuffles (no smem
// epilogue). Parallel polling: lanes 0-3 of warp 0 watch all 4 chunk
// counters and fire each 16KB bulk copy the moment it's ready.
// =====================================================================
__global__ void __launch_bounds__(TPB, 1) lstm_kernel(
    const float* __restrict__ wr,
    float* __restrict__ out_h, float* __restrict__ out_c)
{
    extern __shared__ char smem[];
    const uint32_t sbu = smem_u32(smem);

    const int tid = threadIdx.x;
    const int wid = tid >> 5, lane = tid & 31;
    const int j0 = blockIdx.x * JPC;
    const int s7 = lane & 7;
    const int mychunk = blockIdx.x >> 5;

    if (tid == 0) {
        #pragma unroll
        for (int c = 0; c < 4; c++) MBARRIER_INIT(sbu + MB_OFF + 8 * c, 1);
    }

    // ---- W' staging (plain fp16): rows m 0-15 = col(gate*4+jj) ----
    for (int i = tid; i < 16 * NH; i += TPB) {
        int m = i & 15, k = i >> 4;
        int gate = m >> 2, jj = m & 3;
        float w = wr[(size_t)k * NG4 + gate * NH + j0 + jj];
        *reinterpret_cast<uint16_t*>(smem + WS_OFF + m * 1024 +
            ((((k >> 3) ^ (m & 7)) << 4) | ((k & 7) << 1))) =
            __half_as_ushort(__float2half(w));
    }
    __syncthreads();

    // ---- a-frags: full k=512, m16 ----
    uint32_t ar[32][4];
    {
        int row = ((lane >> 3) & 1) * 8 + s7;
        int acb = lane >> 4;
        uint32_t rbase = sbu + WS_OFF + row * 1024;
        #pragma unroll
        for (int ks = 0; ks < 32; ks++) {
            int chunk = ks * 2 + acb;
            LDSM_X4(ar[ks][0], ar[ks][1], ar[ks][2], ar[ks][3],
                    rbase + ((chunk ^ (row & 7)) << 4));
        }
    }
    __syncthreads();

    // this thread's gate identity: batch = 8*wid + bl, hidden jj
    const int bl = lane & 7;           // local batch in warp's n8 slice
    const int jj = lane >> 3;          // 0..3
    const int gb = wid * 8 + bl;       // global batch
    const int jrow = j0 + jj;
    float c_state = 0.f;

    // b-frag addressing (ldsm.x2): lanes 0-7 rows n0-7 chunk0, 8-15 chunk1
    const int brow = wid * 8 + s7;     // this warp's batch rows
    const int bcb = (lane >> 3) & 1;
    const uint32_t bbase = sbu + H_OFF + brow * 256;

    // gate shuffle sources
    const int lsrc1 = jj * 4 + (bl >> 1);
    const int lsrc2 = lsrc1 + 16;
    const bool bodd = (bl & 1) != 0;

    // producer h-write address (pre-swizzled fp16 image)
    const int kq = jrow & 127;
    const size_t poff = (size_t)(jrow >> 7) * 16384 + (size_t)gb * 256 +
                        (((kq >> 3) ^ (gb & 7)) << 4) + (kq & 7) * 2;

    for (int t = 0; t < NT; t++) {
        // prefetch xw (DRAM; consumed at gates)
        float xwv[4];
        #pragma unroll
        for (int g = 0; g < 4; g++)
            xwv[g] = __ldcg(&g_xw[t][g * NH + jrow][gb]);

        const int buf = t & 1;
        // ---- parallel poll + per-chunk bulk copy (warp 0, lanes 0-3) ----
        if (wid == 0 && lane < 4) {
            const unsigned int tgt = 32u * (unsigned int)t;
            const unsigned int* cp = &g_cbar[lane * 32];
            const uint8_t* hsrc = &g_hb[buf][lane][0][0];
            uint32_t mb = sbu + MB_OFF + 8 * lane;
            uint32_t dsts = sbu + H_OFF + lane * 16384;
            bool issued = false;
            for (;;) {
                unsigned int cur;
                asm volatile("ld.global.acquire.gpu.u32 %0, [%1];"
                             : "=r"(cur) : "l"(cp));
                bool ready = cur >= tgt;
                if (ready && !issued) {
                    MBARRIER_EXPECT_TX(mb, 16384);
                    BULK_G2S(dsts, hsrc, 16384, mb);
                    issued = true;
                }
                if (__all_sync(0x0000000Fu, ready)) break;
            }
        }

        float acc[4];
        acc[0] = acc[1] = acc[2] = acc[3] = 0.f;

        // ---- chunk-ordered MMA: per ks one LDSM.x2 (n8 k16) + 1 MMA ----
        #pragma unroll
        for (int c = 0; c < 4; c++) {
            MBARRIER_WAIT_PARITY(sbu + MB_OFF + 8 * c, t & 1);
            uint32_t base0 = bbase + c * 16384;
            #pragma unroll
            for (int kk = 0; kk < 8; kk++) {
                int ks = c * 8 + kk;
                uint32_t off = (((kk * 2 + bcb) ^ s7) << 4);
                uint32_t b0, b1;
                LDSM_X2(b0, b1, base0 + off);
                MMA_FP16(acc, ar[ks][0], ar[ks][1], ar[ks][2], ar[ks][3], b0, b1);
            }
        }

        // ---- gates fully in-warp: 8 shuffles transpose the z tile ----
        {
            float v0 = __shfl_sync(0xffffffffu, acc[0], lsrc1);
            float v1 = __shfl_sync(0xffffffffu, acc[1], lsrc1);
            float v2 = __shfl_sync(0xffffffffu, acc[2], lsrc1);
            float v3 = __shfl_sync(0xffffffffu, acc[3], lsrc1);
            float w0 = __shfl_sync(0xffffffffu, acc[0], lsrc2);
            float w1 = __shfl_sync(0xffffffffu, acc[1], lsrc2);
            float w2 = __shfl_sync(0xffffffffu, acc[2], lsrc2);
            float w3 = __shfl_sync(0xffffffffu, acc[3], lsrc2);
            float z0 = xwv[0] + (bodd ? v1 : v0);   // gate i  (m=jj)
            float z1 = xwv[1] + (bodd ? w1 : w0);   // gate f  (m=jj+4)
            float z2 = xwv[2] + (bodd ? v3 : v2);   // gate g  (m=jj+8)
            float z3 = xwv[3] + (bodd ? w3 : w2);   // gate o  (m=jj+12)

            float ig = fsig(z0);
            float fg = fsig(z1);
            float gv = ftanh(z2);
            float og = fsig(z3);
            c_state = fg * c_state + ig * gv;
            float hv = og * ftanh(c_state);
            uint8_t* hdst = &g_hb[(t + 1) & 1][0][0][0];
            *reinterpret_cast<uint16_t*>(hdst + poff) =
                __half_as_ushort(__float2half(hv));
            g_hs[t][jrow][gb] = hv;
            if (t == NT - 1) {
                out_h[(size_t)gb * NH + jrow] = hv;
                out_c[(size_t)gb * NH + jrow] = c_state;
            }
        }
        __syncthreads();

        // ---- producer publish: tid0 cumulative fence + one atomic ----
        if (t < NT - 1 && tid == 0) {
            __threadfence();
            atomicAdd(&g_cbar[mychunk * 32], 1u);
        }
    }
}

// ---------------- Dense(32, tanh) over all timesteps ----------------
#define DTPB 256
__global__ void __launch_bounds__(DTPB, 1) dense_kernel(
    const float* __restrict__ dw, const float* __restrict__ db,
    float* __restrict__ out)
{
    extern __shared__ float smemf[];
    float* hsm = smemf;
    float* wsm = smemf + NH * NB;
    int t = blockIdx.x, tid = threadIdx.x;
    {
        const float4* src = reinterpret_cast<const float4*>(&g_hs[t][0][0]);
        float4* dst = reinterpret_cast<float4*>(hsm);
        for (int i = tid; i < NH * NB / 4; i += DTPB) dst[i] = src[i];
        const float4* ws = reinterpret_cast<const float4*>(dw);
        float4* wd = reinterpret_cast<float4*>(wsm);
        for (int i = tid; i < NH * NDS / 4; i += DTPB) wd[i] = ws[i];
    }
    __syncthreads();

    int bg = tid & 15, dg = tid >> 4;
    float acc[4][2];
    #pragma unroll
    for (int bi = 0; bi < 4; bi++) { acc[bi][0] = 0.f; acc[bi][1] = 0.f; }
    #pragma unroll 4
    for (int k = 0; k < NH; k++) {
        float4 hv = *reinterpret_cast<const float4*>(&hsm[k * NB + bg * 4]);
        float2 wv = *reinterpret_cast<const float2*>(&wsm[k * NDS + dg * 2]);
        float hvv[4] = {hv.x, hv.y, hv.z, hv.w};
        #pragma unroll
        for (int bi = 0; bi < 4; bi++) {
            acc[bi][0] += hvv[bi] * wv.x;
            acc[bi][1] += hvv[bi] * wv.y;
        }
    }
    float b0 = db[dg * 2], b1 = db[dg * 2 + 1];
    #pragma unroll
    for (int bi = 0; bi < 4; bi++) {
        int b = bg * 4 + bi;
        size_t base = (size_t)b * NT * NDS + (size_t)t * NDS + dg * 2;
        out[base]     = tanhf(acc[bi][0] + b0);
        out[base + 1] = tanhf(acc[bi][1] + b1);
    }
}

#define DENSE_SMEM ((NH * NB + NH * NDS) * 4)

extern "C" void kernel_launch(void* const* d_in, const int* in_sizes, int n_in,
                              void* d_out, int out_size) {
    const float* x    = (const float*)d_in[0];
    const float* wk   = (const float*)d_in[1];
    const float* wr   = (const float*)d_in[2];
    const float* bias = (const float*)d_in[3];
    const float* dw   = (const float*)d_in[4];
    const float* db   = (const float*)d_in[5];
    float* out   = (float*)d_out;
    float* out_h = out + (size_t)NB * NT * NDS;
    float* out_c = out_h + (size_t)NB * NH;

    cudaFuncSetAttribute(xw_kernel,
                         cudaFuncAttributeMaxDynamicSharedMemorySize, XW_SMEM);
    cudaFuncSetAttribute(lstm_kernel,
                         cudaFuncAttributeMaxDynamicSharedMemorySize, LSTM_SMEM);
    cudaFuncSetAttribute(dense_kernel,
                         cudaFuncAttributeMaxDynamicSharedMemorySize, DENSE_SMEM);

    init_kernel<<<64, 256>>>();                          // 0
    wbf_kernel<<<2 * NG4, ND>>>(wk);                     // 1
    xw_kernel<<<NT, 256, XW_SMEM>>>(x, bias);            // 2
    lstm_kernel<<<G, TPB, LSTM_SMEM>>>(wr, out_h, out_c);// 3  <- profiled slot
    dense_kernel<<<NT, DTPB, DENSE_SMEM>>>(dw, db, out); // 4
}

// round 14
// speedup vs baseline: 3.3571x; 1.2346x over previous
#include <cuda_runtime.h>
#include <cuda_bf16.h>
#include <cuda_fp16.h>
#include <cstdint>
#include <math.h>

// ---------------- problem dims ----------------
#define NB 64
#define NT 512
#define ND 128
#define NH 512
#define NDS 32
#define NG4 (4 * NH)   // 2048

// ---------------- LSTM config ----------------
#define G 128          // persistent CTAs, 1/SM
#define TPB 256        // 8 warps
#define JPC 4          // hidden units per CTA -> 16 true z-cols (m=16, fp16 W)
// SMEM layout (bytes)
#define H_OFF 0                    // h [4 chunks][64 rows][256B] = 65536
#define WS_OFF 65536               // W' staging [16][1024B] = 16384
#define MB_OFF 81920               // 4 mbarriers
#define LSTM_SMEM 81984

__device__ __forceinline__ uint32_t smem_u32(const void* p) {
    uint32_t a;
    asm("{ .reg .u64 t; cvta.to.shared.u64 t, %1; cvt.u32.u64 %0, t; }" : "=r"(a) : "l"(p));
    return a;
}
// fast gate nonlinearities (MUFU-based)
__device__ __forceinline__ float fsig(float x) { return 1.f / (1.f + __expf(-x)); }
__device__ __forceinline__ float ftanh(float x) {
    float ax = fabsf(x);
    float e = __expf(-2.f * ax);
    float r = (1.f - e) / (1.f + e);
    return copysignf(r, x);
}

__device__ __forceinline__ uint4 pack_f16_8(float4 a, float4 b) {
    uint4 r;
    r.x = (uint32_t)__half_as_ushort(__float2half(a.x)) |
          ((uint32_t)__half_as_ushort(__float2half(a.y)) << 16);
    r.y = (uint32_t)__half_as_ushort(__float2half(a.z)) |
          ((uint32_t)__half_as_ushort(__float2half(a.w)) << 16);
    r.z = (uint32_t)__half_as_ushort(__float2half(b.x)) |
          ((uint32_t)__half_as_ushort(__float2half(b.y)) << 16);
    r.w = (uint32_t)__half_as_ushort(__float2half(b.z)) |
          ((uint32_t)__half_as_ushort(__float2half(b.w)) << 16);
    return r;
}

#define LDSM_X4(r0, r1, r2, r3, addr) \
    asm volatile("ldmatrix.sync.aligned.m8n8.x4.shared.b16 {%0,%1,%2,%3}, [%4];" \
        : "=r"(r0), "=r"(r1), "=r"(r2), "=r"(r3) : "r"(addr))

#define MMA_FP16(c, a0, a1, a2, a3, b0, b1) \
    asm volatile("mma.sync.aligned.m16n8k16.row.col.f32.f16.f16.f32 " \
        "{%0,%1,%2,%3}, {%4,%5,%6,%7}, {%8,%9}, {%0,%1,%2,%3};" \
        : "+f"((c)[0]), "+f"((c)[1]), "+f"((c)[2]), "+f"((c)[3]) \
        : "r"(a0), "r"(a1), "r"(a2), "r"(a3), "r"(b0), "r"(b1))

#define CP16(dst, src) \
    asm volatile("cp.async.cg.shared.global [%0], [%1], 16;" :: "r"(dst), "l"(src))
#define CP_COMMIT() asm volatile("cp.async.commit_group;" ::: "memory")
#define CP_WAIT(n)  asm volatile("cp.async.wait_group %0;" :: "n"(n) : "memory")
#define MBARRIER_INIT(mbar, cnt) \
    asm volatile("mbarrier.init.shared.b64 [%0], %1;" :: "r"((uint32_t)(mbar)), "r"((uint32_t)(cnt)) : "memory")
#define MBARRIER_EXPECT_TX(mbar, bytes) \
    asm volatile("mbarrier.arrive.expect_tx.shared.b64 _, [%0], %1;" \
                 :: "r"((uint32_t)(mbar)), "r"((uint32_t)(bytes)) : "memory")
#define BULK_G2S(dst, src, bytes, mbar) \
    asm volatile("cp.async.bulk.shared::cta.global.mbarrier::complete_tx::bytes " \
                 "[%0], [%1], %2, [%3];" \
                 :: "r"((uint32_t)(dst)), "l"(src), "r"((uint32_t)(bytes)), \
                    "r"((uint32_t)(mbar)) : "memory")
#define MBARRIER_WAIT_PARITY(mbar, par) do { \
    uint32_t _m = (uint32_t)(mbar); uint32_t _p = (uint32_t)(par); uint32_t _d; \
    asm volatile("{\n\t.reg .pred p;\n\t" \
        "mbarrier.try_wait.parity.acquire.cta.shared::cta.b64 p, [%1], %2;\n\t" \
        "selp.b32 %0, 1, 0, p;\n\t}" : "=r"(_d) : "r"(_m), "r"(_p) : "memory"); \
    if (!_d) { \
        asm volatile("{\n\t.reg .pred P1;\n\t" \
            "WL_%=:\n\t" \
            "mbarrier.try_wait.parity.acquire.cta.shared::cta.b64 P1, [%0], %1, 0x989680;\n\t" \
            "@P1 bra.uni WD_%=;\n\t" \
            "bra.uni WL_%=;\n\t" \
            "WD_%=:\n\t}" :: "r"(_m), "r"(_p) : "memory"); \
    } } while (0)

// ---------------- global scratch ----------------
// h (fp16) in the exact swizzled SMEM image: [buf][chunk(k128)][row=batch][256B]
__device__ __align__(128) uint8_t g_hb[2][4][64][256];
__device__ __half g_wt[NG4][ND];                // wk transposed (fp16)
__device__ float g_xw[NT][NG4][NB];             // x@Wk + bias
__device__ float g_hs[NT][NH][NB];              // hidden states for dense
__device__ unsigned int g_cbar[4 * 32];         // per-chunk monotonic counters

__global__ void init_kernel() {
    int idx = blockIdx.x * blockDim.x + threadIdx.x;
    if (idx < 4 * 32) g_cbar[idx] = 0u;
    uint32_t* p = reinterpret_cast<uint32_t*>(&g_hb[0][0][0][0]);
    for (int i = idx; i < (int)(sizeof(g_hb) / 4); i += gridDim.x * blockDim.x)
        p[i] = 0u;
}

// ---- one-time: transpose + fp16 convert of wk ----
__global__ void wbf_kernel(const float* __restrict__ wk) {
    int n = blockIdx.x;          // 0..2047
    int k = threadIdx.x;         // 0..127
    g_wt[n][k] = __float2half(wk[(size_t)k * NG4 + n]);
}

// =====================================================================
// XW kernel (fp16): g_xw[t][col][b] = x@wk + bias
// m=64 batches, k=128, loop 32 col-blocks of n=64.
// =====================================================================
#define XA_OFF 0           // [64][256B] = 16384
#define XB_OFF 16384       // [64][256B] = 16384
#define XZ_OFF 32768       // zb[64][65] f32 = 16640
#define XW_SMEM 49408

__global__ void __launch_bounds__(256, 1) xw_kernel(
    const float* __restrict__ x, const float* __restrict__ bias)
{
    extern __shared__ char smem[];
    const uint32_t sbu = smem_u32(smem);
    float* zb = reinterpret_cast<float*>(smem + XZ_OFF);
    const int tid = threadIdx.x, wid = tid >> 5, lane = tid & 31;
    const int t = blockIdx.x;
    const int s7 = lane & 7;

    // A staging: x fp16, 64 rows (batch) x 256B (k=128)
    for (int i = tid; i < 64 * 16; i += 256) {
        int b = i >> 4, cs = i & 15;
        const float4* xp = reinterpret_cast<const float4*>(
            x + ((size_t)b * NT + t) * ND + cs * 8);
        *reinterpret_cast<uint4*>(smem + XA_OFF + b * 256 + ((cs ^ (b & 7)) << 4))
            = pack_f16_8(xp[0], xp[1]);
    }
    __syncthreads();

    const int mslice = wid & 3, whalf = wid >> 2;
    uint32_t ar[8][4];
    {
        int row8 = ((lane >> 3) & 1) * 8 + s7;
        int acb = lane >> 4;
        #pragma unroll
        for (int ks = 0; ks < 8; ks++) {
            int row = mslice * 16 + row8;
            uint32_t addr = sbu + XA_OFF + row * 256 +
                (((ks * 2 + acb) ^ (row & 7)) << 4);
            LDSM_X4(ar[ks][0], ar[ks][1], ar[ks][2], ar[ks][3], addr);
        }
    }

    const int browl = ((lane >> 4) << 3) + s7;
    const int bcb = (lane >> 3) & 1;

    for (int cb = 0; cb < 32; cb++) {
        // stream B tile: 64 rows (cols) x 256B = 16KB
        #pragma unroll
        for (int it = 0; it < 4; it++) {
            int i = it * 256 + tid;
            int row = i >> 4, cpi = i & 15;
            const __half* src = &g_wt[cb * 64 + row][cpi * 8];
            uint32_t dst = sbu + XB_OFF + row * 256 + ((cpi ^ (row & 7)) << 4);
            CP16(dst, src);
        }
        CP_COMMIT();
        CP_WAIT(0);
        __syncthreads();

        float acc[4][4];
        #pragma unroll
        for (int nf = 0; nf < 4; nf++)
            #pragma unroll
            for (int q = 0; q < 4; q++) acc[nf][q] = 0.f;

        #pragma unroll
        for (int ks = 0; ks < 8; ks++) {
            #pragma unroll
            for (int q = 0; q < 2; q++) {
                int rowb = whalf * 32 + q * 16 + browl;
                uint32_t baddr = sbu + XB_OFF + rowb * 256 +
                    (((ks * 2 + bcb) ^ s7) << 4);
                uint32_t b0, b1, b2, b3;
                LDSM_X4(b0, b1, b2, b3, baddr);
                MMA_FP16(acc[2 * q],     ar[ks][0], ar[ks][1], ar[ks][2], ar[ks][3], b0, b1);
                MMA_FP16(acc[2 * q + 1], ar[ks][0], ar[ks][1], ar[ks][2], ar[ks][3], b2, b3);
            }
        }

        // epilogue -> zb[batch][col]
        #pragma unroll
        for (int nf = 0; nf < 4; nf++) {
            int m = mslice * 16 + (lane >> 2);
            int c = whalf * 32 + (nf >> 1) * 16 + (nf & 1) * 8 + 2 * (lane & 3);
            zb[(size_t)m * 65 + c]           = acc[nf][0];
            zb[(size_t)m * 65 + c + 1]       = acc[nf][1];
            zb[(size_t)(m + 8) * 65 + c]     = acc[nf][2];
            zb[(size_t)(m + 8) * 65 + c + 1] = acc[nf][3];
        }
        __syncthreads();

        for (int i = tid; i < 64 * 64; i += 256) {
            int b = i & 63, c = i >> 6;
            g_xw[t][cb * 64 + c][b] = zb[(size_t)b * 65 + c] + bias[cb * 64 + c];
        }
        __syncthreads();
    }
}

// =====================================================================
// Persistent LSTM — fp16 W (m16), 8 warps x (m16 x n8), in-warp gates.
// ldsm.x4 covers 2 k-steps per load. Publish via red.release (no fence);
// g_hs store moved off the critical path (after publish).
// =====================================================================
__global__ void __launch_bounds__(TPB, 1) lstm_kernel(
    const float* __restrict__ wr,
    float* __restrict__ out_h, float* __restrict__ out_c)
{
    extern __shared__ char smem[];
    const uint32_t sbu = smem_u32(smem);

    const int tid = threadIdx.x;
    const int wid = tid >> 5, lane = tid & 31;
    const int j0 = blockIdx.x * JPC;
    const int s7 = lane & 7;
    const int mychunk = blockIdx.x >> 5;

    if (tid == 0) {
        #pragma unroll
        for (int c = 0; c < 4; c++) MBARRIER_INIT(sbu + MB_OFF + 8 * c, 1);
    }

    // ---- W' staging (fp16): rows m 0-15 = col(gate*4+jj) ----
    for (int i = tid; i < 16 * NH; i += TPB) {
        int m = i & 15, k = i >> 4;
        int gate = m >> 2, jj = m & 3;
        float w = wr[(size_t)k * NG4 + gate * NH + j0 + jj];
        *reinterpret_cast<uint16_t*>(smem + WS_OFF + m * 1024 +
            ((((k >> 3) ^ (m & 7)) << 4) | ((k & 7) << 1))) =
            __half_as_ushort(__float2half(w));
    }
    __syncthreads();

    // ---- a-frags: full k=512, m16 ----
    uint32_t ar[32][4];
    {
        int row = ((lane >> 3) & 1) * 8 + s7;
        int acb = lane >> 4;
        uint32_t rbase = sbu + WS_OFF + row * 1024;
        #pragma unroll
        for (int ks = 0; ks < 32; ks++) {
            int chunk = ks * 2 + acb;
            LDSM_X4(ar[ks][0], ar[ks][1], ar[ks][2], ar[ks][3],
                    rbase + ((chunk ^ (row & 7)) << 4));
        }
    }
    __syncthreads();

    // this thread's gate identity: batch = 8*wid + bl, hidden jj
    const int bl = lane & 7;
    const int jj = lane >> 3;
    const int gb = wid * 8 + bl;
    const int jrow = j0 + jj;
    float c_state = 0.f;

    // b-frag addressing (ldsm.x4 over 2 ks): lane group g = lane>>3 -> chunk 4*kk2+g
    const int bg4 = lane >> 3;
    const uint32_t bbase = sbu + H_OFF + (wid * 8 + s7) * 256;

    // gate shuffle sources
    const int lsrc1 = jj * 4 + (bl >> 1);
    const int lsrc2 = lsrc1 + 16;
    const bool bodd = (bl & 1) != 0;

    // producer h-write address (pre-swizzled fp16 image)
    const int kq = jrow & 127;
    const size_t poff = (size_t)(jrow >> 7) * 16384 + (size_t)gb * 256 +
                        (((kq >> 3) ^ (gb & 7)) << 4) + (kq & 7) * 2;

    for (int t = 0; t < NT; t++) {
        // prefetch xw (DRAM; consumed at gates)
        float xwv[4];
        #pragma unroll
        for (int g = 0; g < 4; g++)
            xwv[g] = __ldcg(&g_xw[t][g * NH + jrow][gb]);

        const int buf = t & 1;
        // ---- parallel poll + per-chunk bulk copy (warp 0, lanes 0-3) ----
        if (wid == 0 && lane < 4) {
            const unsigned int tgt = 32u * (unsigned int)t;
            const unsigned int* cp = &g_cbar[lane * 32];
            const uint8_t* hsrc = &g_hb[buf][lane][0][0];
            uint32_t mb = sbu + MB_OFF + 8 * lane;
            uint32_t dsts = sbu + H_OFF + lane * 16384;
            bool issued = false;
            for (;;) {
                unsigned int cur;
                asm volatile("ld.global.acquire.gpu.u32 %0, [%1];"
                             : "=r"(cur) : "l"(cp));
                bool ready = cur >= tgt;
                if (ready && !issued) {
                    MBARRIER_EXPECT_TX(mb, 16384);
                    BULK_G2S(dsts, hsrc, 16384, mb);
                    issued = true;
                }
                if (__all_sync(0x0000000Fu, ready)) break;
            }
        }

        float acc[4];
        acc[0] = acc[1] = acc[2] = acc[3] = 0.f;

        // ---- chunk-ordered MMA: per kk2 one LDSM.x4 (n8 k32) + 2 MMA ----
        #pragma unroll
        for (int c = 0; c < 4; c++) {
            MBARRIER_WAIT_PARITY(sbu + MB_OFF + 8 * c, t & 1);
            uint32_t base0 = bbase + c * 16384;
            #pragma unroll
            for (int kk2 = 0; kk2 < 4; kk2++) {
                int ks = c * 8 + kk2 * 2;
                uint32_t off = (((kk2 * 4 + bg4) ^ s7) << 4);
                uint32_t b0, b1, b2, b3;
                LDSM_X4(b0, b1, b2, b3, base0 + off);
                MMA_FP16(acc, ar[ks][0],     ar[ks][1],     ar[ks][2],     ar[ks][3],     b0, b1);
                MMA_FP16(acc, ar[ks + 1][0], ar[ks + 1][1], ar[ks + 1][2], ar[ks + 1][3], b2, b3);
            }
        }

        // ---- gates fully in-warp: 8 shuffles transpose the z tile ----
        float hv;
        {
            float v0 = __shfl_sync(0xffffffffu, acc[0], lsrc1);
            float v1 = __shfl_sync(0xffffffffu, acc[1], lsrc1);
            float v2 = __shfl_sync(0xffffffffu, acc[2], lsrc1);
            float v3 = __shfl_sync(0xffffffffu, acc[3], lsrc1);
            float w0 = __shfl_sync(0xffffffffu, acc[0], lsrc2);
            float w1 = __shfl_sync(0xffffffffu, acc[1], lsrc2);
            float w2 = __shfl_sync(0xffffffffu, acc[2], lsrc2);
            float w3 = __shfl_sync(0xffffffffu, acc[3], lsrc2);
            float z0 = xwv[0] + (bodd ? v1 : v0);
            float z1 = xwv[1] + (bodd ? w1 : w0);
            float z2 = xwv[2] + (bodd ? v3 : v2);
            float z3 = xwv[3] + (bodd ? w3 : w2);

            float ig = fsig(z0);
            float fg = fsig(z1);
            float gv = ftanh(z2);
            float og = fsig(z3);
            c_state = fg * c_state + ig * gv;
            hv = og * ftanh(c_state);
            uint8_t* hdst = &g_hb[(t + 1) & 1][0][0][0];
            *reinterpret_cast<uint16_t*>(hdst + poff) =
                __half_as_ushort(__float2half(hv));
        }
        __syncthreads();

        // ---- publish (release atomic covers all h stores via syncthreads) ----
        if (t < NT - 1 && tid == 0) {
            asm volatile("red.release.gpu.global.add.u32 [%0], %1;"
                         :: "l"(&g_cbar[mychunk * 32]), "r"(1u) : "memory");
        }

        // ---- off-critical-path: hs store for dense + final outputs ----
        g_hs[t][jrow][gb] = hv;
        if (t == NT - 1) {
            out_h[(size_t)gb * NH + jrow] = hv;
            out_c[(size_t)gb * NH + jrow] = c_state;
        }
    }
}

// ---------------- Dense(32, tanh) over all timesteps ----------------
#define DTPB 256
__global__ void __launch_bounds__(DTPB, 1) dense_kernel(
    const float* __restrict__ dw, const float* __restrict__ db,
    float* __restrict__ out)
{
    extern __shared__ float smemf[];
    float* hsm = smemf;
    float* wsm = smemf + NH * NB;
    int t = blockIdx.x, tid = threadIdx.x;
    {
        const float4* src = reinterpret_cast<const float4*>(&g_hs[t][0][0]);
        float4* dst = reinterpret_cast<float4*>(hsm);
        for (int i = tid; i < NH * NB / 4; i += DTPB) dst[i] = src[i];
        const float4* ws = reinterpret_cast<const float4*>(dw);
        float4* wd = reinterpret_cast<float4*>(wsm);
        for (int i = tid; i < NH * NDS / 4; i += DTPB) wd[i] = ws[i];
    }
    __syncthreads();

    int bg = tid & 15, dg = tid >> 4;
    float acc[4][2];
    #pragma unroll
    for (int bi = 0; bi < 4; bi++) { acc[bi][0] = 0.f; acc[bi][1] = 0.f; }
    #pragma unroll 4
    for (int k = 0; k < NH; k++) {
        float4 hv = *reinterpret_cast<const float4*>(&hsm[k * NB + bg * 4]);
        float2 wv = *reinterpret_cast<const float2*>(&wsm[k * NDS + dg * 2]);
        float hvv[4] = {hv.x, hv.y, hv.z, hv.w};
        #pragma unroll
        for (int bi = 0; bi < 4; bi++) {
            acc[bi][0] += hvv[bi] * wv.x;
            acc[bi][1] += hvv[bi] * wv.y;
        }
    }
    float b0 = db[dg * 2], b1 = db[dg * 2 + 1];
    #pragma unroll
    for (int bi = 0; bi < 4; bi++) {
        int b = bg * 4 + bi;
        size_t base = (size_t)b * NT * NDS + (size_t)t * NDS + dg * 2;
        out[base]     = tanhf(acc[bi][0] + b0);
        out[base + 1] = tanhf(acc[bi][1] + b1);
    }
}

#define DENSE_SMEM ((NH * NB + NH * NDS) * 4)

extern "C" void kernel_launch(void* const* d_in, const int* in_sizes, int n_in,
                              void* d_out, int out_size) {
    const float* x    = (const float*)d_in[0];
    const float* wk   = (const float*)d_in[1];
    const float* wr   = (const float*)d_in[2];
    const float* bias = (const float*)d_in[3];
    const float* dw   = (const float*)d_in[4];
    const float* db   = (const float*)d_in[5];
    float* out   = (float*)d_out;
    float* out_h = out + (size_t)NB * NT * NDS;
    float* out_c = out_h + (size_t)NB * NH;

    cudaFuncSetAttribute(xw_kernel,
                         cudaFuncAttributeMaxDynamicSharedMemorySize, XW_SMEM);
    cudaFuncSetAttribute(lstm_kernel,
                         cudaFuncAttributeMaxDynamicSharedMemorySize, LSTM_SMEM);
    cudaFuncSetAttribute(dense_kernel,
                         cudaFuncAttributeMaxDynamicSharedMemorySize, DENSE_SMEM);

    init_kernel<<<64, 256>>>();                          // 0
    wbf_kernel<<<NG4, ND>>>(wk);                         // 1
    xw_kernel<<<NT, 256, XW_SMEM>>>(x, bias);            // 2
    lstm_kernel<<<G, TPB, LSTM_SMEM>>>(wr, out_h, out_c);// 3  <- profiled slot
    dense_kernel<<<NT, DTPB, DENSE_SMEM>>>(dw, db, out); // 4
}